// round 1
// baseline (speedup 1.0000x reference)
#include <cuda_runtime.h>
#include <math.h>

static constexpr int B_ = 16, C_ = 256, H_ = 1024, S_ = 1024, E_ = 512;
static constexpr int NH_ = 8, HD_ = 64, DD_ = 512, DS_ = 64;
static constexpr int S1_ = S_ + 1;
static constexpr int RELM = 2048;

// ---------------- device scratch (allocation-free) ----------------
__device__ float g_static_token[B_ * E_];
__device__ float g_hidden[B_ * E_];
__device__ float g_film[B_ * C_];
__device__ float g_Wq_comb[E_ * C_];
__device__ float g_bq_comb[E_];
__device__ float g_Wk_dyn[E_ * DD_];
__device__ float g_Wv_dyn[E_ * DD_];
__device__ float g_bk[E_];
__device__ float g_bv[E_];
__device__ float g_Wco[C_ * E_];
__device__ float g_bco[C_];
__device__ float g_q[(size_t)B_ * H_ * E_];
__device__ float g_k[(size_t)B_ * S1_ * E_];
__device__ float g_v[(size_t)B_ * S1_ * E_];
__device__ float g_ctx[(size_t)B_ * H_ * E_];

// ---------------- swizzled transposed 64x64 tiles ----------------
// Tile stored as T[k][m], element (k,m) at swz(k,m). XOR swizzle keeps float4
// groups (low 2 bits of m) contiguous and spreads banks across k.
__device__ __forceinline__ int swz(int r, int c) {
    return (r << 6) + (((c & 60) ^ ((r & 15) << 2)) | (c & 3));
}
__device__ __forceinline__ int swz4(int r, int c4) {  // c4 multiple of 4
    return (r << 6) + (c4 ^ ((r & 15) << 2));
}

// load 64(m) x 64(k) tile from row-major global (row stride ld) into T[k][m]
__device__ __forceinline__ void load_tileT_rm(float* sm, const float* g, int ld) {
    int tid = threadIdx.x;
#pragma unroll
    for (int i = 0; i < 4; i++) {
        int fi = tid + (i << 8);
        int m = fi >> 4;
        int k4 = (fi & 15) << 2;
        float4 v = *reinterpret_cast<const float4*>(g + (size_t)m * ld + k4);
        sm[swz(k4 + 0, m)] = v.x;
        sm[swz(k4 + 1, m)] = v.y;
        sm[swz(k4 + 2, m)] = v.z;
        sm[swz(k4 + 3, m)] = v.w;
    }
}

// col-major A: element (m,k) at g[k*ldk + m] (m contiguous)
__device__ __forceinline__ void load_tileT_cm(float* sm, const float* g, int ldk) {
    int tid = threadIdx.x;
#pragma unroll
    for (int i = 0; i < 4; i++) {
        int fi = tid + (i << 8);
        int k = fi >> 4;
        int m4 = (fi & 15) << 2;
        float4 v = *reinterpret_cast<const float4*>(g + (size_t)k * ldk + m4);
        *reinterpret_cast<float4*>(sm + swz4(k, m4)) = v;
    }
}

// acc[i] holds row m0+i, 4 cols n0..n0+3
__device__ __forceinline__ void mm_chunk(const float* __restrict__ AsT,
                                         const float* __restrict__ WsT,
                                         float4 acc[4], int m0, int n0) {
#pragma unroll 8
    for (int k = 0; k < 64; k++) {
        float4 a = *reinterpret_cast<const float4*>(AsT + swz4(k, m0));
        float4 w = *reinterpret_cast<const float4*>(WsT + swz4(k, n0));
        acc[0].x += a.x * w.x; acc[0].y += a.x * w.y; acc[0].z += a.x * w.z; acc[0].w += a.x * w.w;
        acc[1].x += a.y * w.x; acc[1].y += a.y * w.y; acc[1].z += a.y * w.z; acc[1].w += a.y * w.w;
        acc[2].x += a.z * w.x; acc[2].y += a.z * w.y; acc[2].z += a.z * w.z; acc[2].w += a.z * w.w;
        acc[3].x += a.w * w.x; acc[3].y += a.w * w.y; acc[3].z += a.w * w.z; acc[3].w += a.w * w.w;
    }
}

// ---------------- small conditioning kernels ----------------
__global__ void __launch_bounds__(256) k_static(const float* __restrict__ st,
                                                const float* __restrict__ stat_W,
                                                const float* __restrict__ stat_b) {
    int idx = blockIdx.x * 256 + threadIdx.x;  // B*E
    int b = idx >> 9, e = idx & 511;
    float s = stat_b[e];
    const float* a = st + b * DS_;
    const float* w = stat_W + e * DS_;
#pragma unroll 8
    for (int d = 0; d < DS_; d++) s += a[d] * w[d];
    g_static_token[idx] = s;
}

__global__ void __launch_bounds__(256) k_hidden(const float* __restrict__ W1,
                                                const float* __restrict__ b1) {
    int idx = blockIdx.x * 256 + threadIdx.x;  // B*E
    int b = idx >> 9, e = idx & 511;
    float s = b1[e];
    const float* a = g_static_token + b * E_;
    const float* w = W1 + (size_t)e * E_;
#pragma unroll 8
    for (int i = 0; i < E_; i++) s += a[i] * w[i];
    g_hidden[idx] = s >= 0.f ? s : 0.1f * s;
}

__global__ void __launch_bounds__(256) k_film(const float* __restrict__ W2,
                                              const float* __restrict__ b2) {
    int idx = blockIdx.x * 256 + threadIdx.x;  // B*C
    int b = idx >> 8, c = idx & 255;
    float s = b2[c];
    const float* a = g_hidden + b * E_;
    const float* w = W2 + (size_t)c * E_;
#pragma unroll 8
    for (int i = 0; i < E_; i++) s += a[i] * w[i];
    g_film[idx] = tanhf(s);
}

// out[n,m] = sum_k L[n,k]*R[k,m]
__global__ void __launch_bounds__(256) comb_kernel(int target, const float* __restrict__ L,
                                                   const float* __restrict__ R,
                                                   int M, int K, int ldL, int ldR) {
    int idx = blockIdx.x * 256 + threadIdx.x;
    int nn = idx / M, mm = idx - nn * M;
    float s = 0.f;
#pragma unroll 8
    for (int k2 = 0; k2 < K; k2++) s += L[(size_t)nn * ldL + k2] * R[(size_t)k2 * ldR + mm];
    float* o = (target == 0) ? g_Wq_comb : (target == 1) ? g_Wk_dyn
             : (target == 2) ? g_Wv_dyn : g_Wco;
    o[idx] = s;
}

__global__ void __launch_bounds__(256) biasc_kernel(int target, const float* __restrict__ L,
                                                    int ldL, const float* __restrict__ vec,
                                                    const float* __restrict__ addv, int K) {
    int n = blockIdx.x * 256 + threadIdx.x;
    float s = addv[n];
#pragma unroll 8
    for (int k = 0; k < K; k++) s += L[(size_t)n * ldL + k] * vec[k];
    float* o = (target == 0) ? g_bq_comb : (target == 1) ? g_bk
             : (target == 2) ? g_bv : g_bco;
    o[n] = s;
}

// k/v row for the static token (position S)
__global__ void __launch_bounds__(256) stat_kv_kernel(const float* __restrict__ in_proj_W,
                                                      const float* __restrict__ in_proj_b) {
    int idx = blockIdx.x * 256 + threadIdx.x;  // 2*B*E
    int which = idx >> 13;
    int r2 = idx & 8191;
    int b = r2 >> 9, e = r2 & 511;
    const float* W = in_proj_W + (size_t)(1 + which) * E_ * E_ + (size_t)e * E_;
    float s = in_proj_b[(1 + which) * E_ + e];
    const float* a = g_static_token + b * E_;
#pragma unroll 8
    for (int i = 0; i < E_; i++) s += a[i] * W[i];
    float* dst = which ? g_v : g_k;
    dst[((size_t)(b * S1_ + S_)) * E_ + e] = s;
}

// ---------------- big GEMMs ----------------
__global__ void __launch_bounds__(256) kv_gemm(const float* __restrict__ dyn, int which) {
    __shared__ float AsT[4096], WsT[4096];
    int nb = blockIdx.x, mb = blockIdx.y;
    int tid = threadIdx.x, ty = tid >> 4, tx = tid & 15;
    const float* W = which ? g_Wv_dyn : g_Wk_dyn;
    const float* bias = which ? g_bv : g_bk;
    float* outp = which ? g_v : g_k;
    const float* Ag = dyn + (size_t)(mb * 64) * DD_;
    const float* Wg = W + (size_t)(nb * 64) * DD_;
    float4 acc[4] = {};
    for (int kc = 0; kc < DD_; kc += 64) {
        load_tileT_rm(AsT, Ag + kc, DD_);
        load_tileT_rm(WsT, Wg + kc, DD_);
        __syncthreads();
        mm_chunk(AsT, WsT, acc, ty << 2, tx << 2);
        __syncthreads();
    }
    int n0 = nb * 64 + (tx << 2);
    float4 bv4 = *reinterpret_cast<const float4*>(bias + n0);
#pragma unroll
    for (int i = 0; i < 4; i++) {
        int row = mb * 64 + (ty << 2) + i;
        int b = row >> 10, s = row & 1023;
        float4 r = acc[i];
        r.x += bv4.x; r.y += bv4.y; r.z += bv4.z; r.w += bv4.w;
        *reinterpret_cast<float4*>(outp + ((size_t)(b * S1_ + s)) * E_ + n0) = r;
    }
}

__global__ void __launch_bounds__(256) q_gemm(const float* __restrict__ x) {
    __shared__ float AsT[4096], WsT[4096];
    int nb = blockIdx.x, mb = blockIdx.y;
    int tid = threadIdx.x, ty = tid >> 4, tx = tid & 15;
    int row0 = mb * 64;
    int b = row0 >> 10, h0 = row0 & 1023;
    const float* Ag = x + (size_t)b * C_ * H_ + h0;  // element (m,k): + k*H + m
    const float* Wg = g_Wq_comb + (size_t)(nb * 64) * C_;
    float4 acc[4] = {};
    for (int kc = 0; kc < C_; kc += 64) {
        load_tileT_cm(AsT, Ag + (size_t)kc * H_, H_);
        load_tileT_rm(WsT, Wg + kc, C_);
        __syncthreads();
        mm_chunk(AsT, WsT, acc, ty << 2, tx << 2);
        __syncthreads();
    }
    int n0 = nb * 64 + (tx << 2);
    float4 bv4 = *reinterpret_cast<const float4*>(g_bq_comb + n0);
#pragma unroll
    for (int i = 0; i < 4; i++) {
        int row = row0 + (ty << 2) + i;
        float4 r = acc[i];
        r.x += bv4.x; r.y += bv4.y; r.z += bv4.z; r.w += bv4.w;
        *reinterpret_cast<float4*>(g_q + (size_t)row * E_ + n0) = r;
    }
}

__global__ void __launch_bounds__(256) out_gemm(const float* __restrict__ x,
                                                float* __restrict__ out) {
    __shared__ float AsT[4096], WsT[4096];
    int nb = blockIdx.x;  // h tile
    int mb = blockIdx.y;  // c tile
    int b = blockIdx.z;
    int tid = threadIdx.x, ty = tid >> 4, tx = tid & 15;
    const float* Ag = g_Wco + (size_t)(mb * 64) * E_;
    const float* Bg = g_ctx + ((size_t)b * H_ + nb * 64) * E_;
    float4 acc[4] = {};
    for (int kc = 0; kc < E_; kc += 64) {
        load_tileT_rm(AsT, Ag + kc, E_);
        load_tileT_rm(WsT, Bg + kc, E_);
        __syncthreads();
        mm_chunk(AsT, WsT, acc, ty << 2, tx << 2);
        __syncthreads();
    }
    int h0n = nb * 64 + (tx << 2);
#pragma unroll
    for (int i = 0; i < 4; i++) {
        int c = mb * 64 + (ty << 2) + i;
        float sc = 1.f + g_film[b * C_ + c];
        float bb = g_bco[c];
        size_t off = ((size_t)b * C_ + c) * H_ + h0n;
        float4 xv = *reinterpret_cast<const float4*>(x + off);
        float4 r;
        r.x = (xv.x + acc[i].x + bb) * sc;
        r.y = (xv.y + acc[i].y + bb) * sc;
        r.z = (xv.z + acc[i].z + bb) * sc;
        r.w = (xv.w + acc[i].w + bb) * sc;
        *reinterpret_cast<float4*>(out + off) = r;
    }
}

// ---------------- fused flash attention ----------------
static constexpr int ATTN_SMEM = (4 * 4096 + 192) * 4;

__global__ void __launch_bounds__(256) attn_kernel(const float* __restrict__ bias_table) {
    extern __shared__ float sm[];
    float* QsT = sm;
    float* KsT = sm + 4096;
    float* SsT = sm + 8192;
    float* Vs  = sm + 12288;  // natural [c][d]
    float* mrow = sm + 16384;
    float* lrow = sm + 16448;
    float* srow = sm + 16512;

    int qt = 15 - blockIdx.x;  // heavy tiles launch first
    int n = blockIdx.y, b = blockIdx.z;
    int h0 = qt << 6;
    int tid = threadIdx.x, ty = tid >> 4, tx = tid & 15;
    int r0 = ty << 2, c0 = tx << 2;

    load_tileT_rm(QsT, g_q + ((size_t)(b * H_ + h0)) * E_ + n * HD_, E_);
    if (tid < 64) { mrow[tid] = -1e30f; lrow[tid] = 0.f; }
    float4 o0 = {}, o1 = {}, o2 = {}, o3 = {};
    __syncthreads();

    for (int it = 0; it <= qt + 1; it++) {
        int kt = (it <= qt) ? it : 16;
        int k0 = kt << 6;
        int nvalid = (kt == 16) ? 1 : 64;
        const float* kg = g_k + ((size_t)(b * S1_ + k0)) * E_ + n * HD_;
        const float* vg = g_v + ((size_t)(b * S1_ + k0)) * E_ + n * HD_;
#pragma unroll
        for (int i = 0; i < 4; i++) {
            int fi = tid + (i << 8);
            int c = fi >> 4;
            int d4 = (fi & 15) << 2;
            float4 kv4 = make_float4(0.f, 0.f, 0.f, 0.f);
            float4 vv4 = make_float4(0.f, 0.f, 0.f, 0.f);
            if (c < nvalid) {
                kv4 = *reinterpret_cast<const float4*>(kg + (size_t)c * E_ + d4);
                vv4 = *reinterpret_cast<const float4*>(vg + (size_t)c * E_ + d4);
            }
            KsT[swz(d4 + 0, c)] = kv4.x;
            KsT[swz(d4 + 1, c)] = kv4.y;
            KsT[swz(d4 + 2, c)] = kv4.z;
            KsT[swz(d4 + 3, c)] = kv4.w;
            *reinterpret_cast<float4*>(Vs + (c << 6) + d4) = vv4;
        }
        __syncthreads();

        float4 sa[4] = {};
        mm_chunk(QsT, KsT, sa, r0, c0);
        // store scores transposed: SsT[c][r]
        *reinterpret_cast<float4*>(SsT + swz4(c0 + 0, r0)) = make_float4(sa[0].x, sa[1].x, sa[2].x, sa[3].x);
        *reinterpret_cast<float4*>(SsT + swz4(c0 + 1, r0)) = make_float4(sa[0].y, sa[1].y, sa[2].y, sa[3].y);
        *reinterpret_cast<float4*>(SsT + swz4(c0 + 2, r0)) = make_float4(sa[0].z, sa[1].z, sa[2].z, sa[3].z);
        *reinterpret_cast<float4*>(SsT + swz4(c0 + 3, r0)) = make_float4(sa[0].w, sa[1].w, sa[2].w, sa[3].w);
        __syncthreads();

        // online softmax: 4 threads per row, 16 cols each
        {
            int r = tid >> 2, seg = tid & 3;
            int h = h0 + r;
            float vals[16];
            float mloc = -1e30f;
#pragma unroll
            for (int j = 0; j < 16; j++) {
                int c = (seg << 4) + j;
                int kk = k0 + c;
                float val = -1e30f;
                if (kk < S1_ && !((kk < S_) && (kk > h))) {
                    val = SsT[swz(c, r)] * 0.125f + __ldg(bias_table + (h - kk + RELM - 1));
                }
                vals[j] = val;
                mloc = fmaxf(mloc, val);
            }
            mloc = fmaxf(mloc, __shfl_xor_sync(0xffffffffu, mloc, 1));
            mloc = fmaxf(mloc, __shfl_xor_sync(0xffffffffu, mloc, 2));
            float mold = mrow[r];
            float mnew = fmaxf(mold, mloc);
            float suml = 0.f;
#pragma unroll
            for (int j = 0; j < 16; j++) {
                int c = (seg << 4) + j;
                float p = __expf(vals[j] - mnew);
                suml += p;
                SsT[swz(c, r)] = p;
            }
            suml += __shfl_xor_sync(0xffffffffu, suml, 1);
            suml += __shfl_xor_sync(0xffffffffu, suml, 2);
            if (seg == 0) {
                float scl = __expf(mold - mnew);
                srow[r] = scl;
                lrow[r] = lrow[r] * scl + suml;
                mrow[r] = mnew;
            }
        }
        __syncthreads();

        // rescale O, accumulate P @ V
        {
            float sA = srow[r0 + 0], sB = srow[r0 + 1], sC = srow[r0 + 2], sD = srow[r0 + 3];
            o0.x *= sA; o0.y *= sA; o0.z *= sA; o0.w *= sA;
            o1.x *= sB; o1.y *= sB; o1.z *= sB; o1.w *= sB;
            o2.x *= sC; o2.y *= sC; o2.z *= sC; o2.w *= sC;
            o3.x *= sD; o3.y *= sD; o3.z *= sD; o3.w *= sD;
#pragma unroll 8
            for (int c = 0; c < 64; c++) {
                float4 p = *reinterpret_cast<const float4*>(SsT + swz4(c, r0));
                float4 vv = *reinterpret_cast<const float4*>(Vs + (c << 6) + c0);
                o0.x += p.x * vv.x; o0.y += p.x * vv.y; o0.z += p.x * vv.z; o0.w += p.x * vv.w;
                o1.x += p.y * vv.x; o1.y += p.y * vv.y; o1.z += p.y * vv.z; o1.w += p.y * vv.w;
                o2.x += p.z * vv.x; o2.y += p.z * vv.y; o2.z += p.z * vv.z; o2.w += p.z * vv.w;
                o3.x += p.w * vv.x; o3.y += p.w * vv.y; o3.z += p.w * vv.z; o3.w += p.w * vv.w;
            }
        }
        __syncthreads();
    }

    float i0 = 1.f / lrow[r0 + 0];
    float i1 = 1.f / lrow[r0 + 1];
    float i2 = 1.f / lrow[r0 + 2];
    float i3 = 1.f / lrow[r0 + 3];
    float* cp = g_ctx + ((size_t)(b * H_ + h0 + r0)) * E_ + n * HD_ + c0;
    float4 w0 = make_float4(o0.x * i0, o0.y * i0, o0.z * i0, o0.w * i0);
    float4 w1 = make_float4(o1.x * i1, o1.y * i1, o1.z * i1, o1.w * i1);
    float4 w2 = make_float4(o2.x * i2, o2.y * i2, o2.z * i2, o2.w * i2);
    float4 w3 = make_float4(o3.x * i3, o3.y * i3, o3.z * i3, o3.w * i3);
    *reinterpret_cast<float4*>(cp + 0 * E_) = w0;
    *reinterpret_cast<float4*>(cp + 1 * E_) = w1;
    *reinterpret_cast<float4*>(cp + 2 * E_) = w2;
    *reinterpret_cast<float4*>(cp + 3 * E_) = w3;
}

// ---------------- launch ----------------
extern "C" void kernel_launch(void* const* d_in, const int* in_sizes, int n_in,
                              void* d_out, int out_size) {
    const float* x         = (const float*)d_in[0];
    const float* dyn       = (const float*)d_in[1];
    const float* statin    = (const float*)d_in[2];
    const float* dyn_W     = (const float*)d_in[3];
    const float* dyn_b     = (const float*)d_in[4];
    const float* stat_W    = (const float*)d_in[5];
    const float* stat_b    = (const float*)d_in[6];
    const float* film_W1   = (const float*)d_in[7];
    const float* film_b1   = (const float*)d_in[8];
    const float* film_W2   = (const float*)d_in[9];
    const float* film_b2   = (const float*)d_in[10];
    const float* q_W       = (const float*)d_in[11];
    const float* q_b       = (const float*)d_in[12];
    const float* in_proj_W = (const float*)d_in[13];
    const float* in_proj_b = (const float*)d_in[14];
    const float* out_W     = (const float*)d_in[15];
    const float* out_b     = (const float*)d_in[16];
    const float* ctx_W     = (const float*)d_in[17];
    const float* ctx_b     = (const float*)d_in[18];
    const float* bias_tab  = (const float*)d_in[19];
    float* out = (float*)d_out;

    cudaFuncSetAttribute(attn_kernel, cudaFuncAttributeMaxDynamicSharedMemorySize, ATTN_SMEM);

    // conditioning path
    k_static<<<(B_ * E_) / 256, 256>>>(statin, stat_W, stat_b);
    k_hidden<<<(B_ * E_) / 256, 256>>>(film_W1, film_b1);
    k_film<<<(B_ * C_) / 256, 256>>>(film_W2, film_b2);

    // fused weight precompute
    comb_kernel<<<(E_ * C_) / 256, 256>>>(0, in_proj_W, q_W, C_, E_, E_, C_);
    comb_kernel<<<(E_ * DD_) / 256, 256>>>(1, in_proj_W + E_ * E_, dyn_W, DD_, E_, E_, DD_);
    comb_kernel<<<(E_ * DD_) / 256, 256>>>(2, in_proj_W + 2 * E_ * E_, dyn_W, DD_, E_, E_, DD_);
    comb_kernel<<<(C_ * E_) / 256, 256>>>(3, ctx_W, out_W, E_, E_, E_, E_);
    biasc_kernel<<<2, 256>>>(0, in_proj_W, E_, q_b, in_proj_b, E_);
    biasc_kernel<<<2, 256>>>(1, in_proj_W + E_ * E_, E_, dyn_b, in_proj_b + E_, E_);
    biasc_kernel<<<2, 256>>>(2, in_proj_W + 2 * E_ * E_, E_, dyn_b, in_proj_b + 2 * E_, E_);
    biasc_kernel<<<1, 256>>>(3, ctx_W, E_, out_b, ctx_b, E_);
    stat_kv_kernel<<<(2 * B_ * E_) / 256, 256>>>(in_proj_W, in_proj_b);

    // projections
    kv_gemm<<<dim3(8, 256), 256>>>(dyn, 0);
    kv_gemm<<<dim3(8, 256), 256>>>(dyn, 1);
    q_gemm<<<dim3(8, 256), 256>>>(x);

    // attention
    attn_kernel<<<dim3(16, NH_, B_), 256, ATTN_SMEM>>>(bias_tab);

    // output projection + residual + FiLM
    out_gemm<<<dim3(16, 4, 16), 256>>>(x, out);

    (void)in_sizes; (void)n_in; (void)out_size;
}

// round 4
// speedup vs baseline: 1.0026x; 1.0026x over previous
#include <cuda_runtime.h>
#include <math.h>

static constexpr int B_ = 16, C_ = 256, H_ = 1024, S_ = 1024, E_ = 512;
static constexpr int NH_ = 8, HD_ = 64, DD_ = 512, DS_ = 64;
static constexpr int S1_ = S_ + 1;
static constexpr int RELM = 2048;

// ---------------- device scratch (allocation-free) ----------------
__device__ float g_static_token[B_ * E_];
__device__ float g_hidden[B_ * E_];
__device__ float g_film[B_ * C_];
__device__ float g_Wq_comb[E_ * C_];
__device__ float g_bq_comb[E_];
__device__ float g_Wk_dyn[E_ * DD_];
__device__ float g_Wv_dyn[E_ * DD_];
__device__ float g_bk[E_];
__device__ float g_bv[E_];
__device__ float g_Wco[C_ * E_];
__device__ float g_bco[C_];
__device__ float g_q[(size_t)B_ * H_ * E_];
__device__ float g_k[(size_t)B_ * S1_ * E_];
__device__ float g_v[(size_t)B_ * S1_ * E_];
__device__ float g_ctx[(size_t)B_ * H_ * E_];

// ---------------- swizzled transposed 64x64 tiles ----------------
// Tile stored as T[k][m], element (k,m) at swz(k,m). XOR swizzle keeps float4
// groups (low 2 bits of m) contiguous and spreads banks across k.
__device__ __forceinline__ int swz(int r, int c) {
    return (r << 6) + (((c & 60) ^ ((r & 15) << 2)) | (c & 3));
}
__device__ __forceinline__ int swz4(int r, int c4) {  // c4 multiple of 4
    return (r << 6) + (c4 ^ ((r & 15) << 2));
}

// load 64(m) x 64(k) tile from row-major global (row stride ld) into T[k][m]
__device__ __forceinline__ void load_tileT_rm(float* sm, const float* g, int ld) {
    int tid = threadIdx.x;
#pragma unroll
    for (int i = 0; i < 4; i++) {
        int fi = tid + (i << 8);
        int m = fi >> 4;
        int k4 = (fi & 15) << 2;
        float4 v = *reinterpret_cast<const float4*>(g + (size_t)m * ld + k4);
        sm[swz(k4 + 0, m)] = v.x;
        sm[swz(k4 + 1, m)] = v.y;
        sm[swz(k4 + 2, m)] = v.z;
        sm[swz(k4 + 3, m)] = v.w;
    }
}

// col-major A: element (m,k) at g[k*ldk + m] (m contiguous)
__device__ __forceinline__ void load_tileT_cm(float* sm, const float* g, int ldk) {
    int tid = threadIdx.x;
#pragma unroll
    for (int i = 0; i < 4; i++) {
        int fi = tid + (i << 8);
        int k = fi >> 4;
        int m4 = (fi & 15) << 2;
        float4 v = *reinterpret_cast<const float4*>(g + (size_t)k * ldk + m4);
        *reinterpret_cast<float4*>(sm + swz4(k, m4)) = v;
    }
}

// acc[i] holds row m0+i, 4 cols n0..n0+3
__device__ __forceinline__ void mm_chunk(const float* __restrict__ AsT,
                                         const float* __restrict__ WsT,
                                         float4 acc[4], int m0, int n0) {
#pragma unroll 8
    for (int k = 0; k < 64; k++) {
        float4 a = *reinterpret_cast<const float4*>(AsT + swz4(k, m0));
        float4 w = *reinterpret_cast<const float4*>(WsT + swz4(k, n0));
        acc[0].x += a.x * w.x; acc[0].y += a.x * w.y; acc[0].z += a.x * w.z; acc[0].w += a.x * w.w;
        acc[1].x += a.y * w.x; acc[1].y += a.y * w.y; acc[1].z += a.y * w.z; acc[1].w += a.y * w.w;
        acc[2].x += a.z * w.x; acc[2].y += a.z * w.y; acc[2].z += a.z * w.z; acc[2].w += a.z * w.w;
        acc[3].x += a.w * w.x; acc[3].y += a.w * w.y; acc[3].z += a.w * w.z; acc[3].w += a.w * w.w;
    }
}

// ---------------- small conditioning kernels ----------------
__global__ void __launch_bounds__(256) k_static(const float* __restrict__ st,
                                                const float* __restrict__ stat_W,
                                                const float* __restrict__ stat_b) {
    int idx = blockIdx.x * 256 + threadIdx.x;  // B*E
    int b = idx >> 9, e = idx & 511;
    float s = stat_b[e];
    const float* a = st + b * DS_;
    const float* w = stat_W + e * DS_;
#pragma unroll 8
    for (int d = 0; d < DS_; d++) s += a[d] * w[d];
    g_static_token[idx] = s;
}

__global__ void __launch_bounds__(256) k_hidden(const float* __restrict__ W1,
                                                const float* __restrict__ b1) {
    int idx = blockIdx.x * 256 + threadIdx.x;  // B*E
    int b = idx >> 9, e = idx & 511;
    float s = b1[e];
    const float* a = g_static_token + b * E_;
    const float* w = W1 + (size_t)e * E_;
#pragma unroll 8
    for (int i = 0; i < E_; i++) s += a[i] * w[i];
    g_hidden[idx] = s >= 0.f ? s : 0.1f * s;
}

__global__ void __launch_bounds__(256) k_film(const float* __restrict__ W2,
                                              const float* __restrict__ b2) {
    int idx = blockIdx.x * 256 + threadIdx.x;  // B*C
    int b = idx >> 8, c = idx & 255;
    float s = b2[c];
    const float* a = g_hidden + b * E_;
    const float* w = W2 + (size_t)c * E_;
#pragma unroll 8
    for (int i = 0; i < E_; i++) s += a[i] * w[i];
    g_film[idx] = tanhf(s);
}

// out[n,m] = sum_k L[n,k]*R[k,m]
__global__ void __launch_bounds__(256) comb_kernel(int target, const float* __restrict__ L,
                                                   const float* __restrict__ R,
                                                   int M, int K, int ldL, int ldR) {
    int idx = blockIdx.x * 256 + threadIdx.x;
    int nn = idx / M, mm = idx - nn * M;
    float s = 0.f;
#pragma unroll 8
    for (int k2 = 0; k2 < K; k2++) s += L[(size_t)nn * ldL + k2] * R[(size_t)k2 * ldR + mm];
    float* o = (target == 0) ? g_Wq_comb : (target == 1) ? g_Wk_dyn
             : (target == 2) ? g_Wv_dyn : g_Wco;
    o[idx] = s;
}

__global__ void __launch_bounds__(256) biasc_kernel(int target, const float* __restrict__ L,
                                                    int ldL, const float* __restrict__ vec,
                                                    const float* __restrict__ addv, int K) {
    int n = blockIdx.x * 256 + threadIdx.x;
    float s = addv[n];
#pragma unroll 8
    for (int k = 0; k < K; k++) s += L[(size_t)n * ldL + k] * vec[k];
    float* o = (target == 0) ? g_bq_comb : (target == 1) ? g_bk
             : (target == 2) ? g_bv : g_bco;
    o[n] = s;
}

// k/v row for the static token (position S)
__global__ void __launch_bounds__(256) stat_kv_kernel(const float* __restrict__ in_proj_W,
                                                      const float* __restrict__ in_proj_b) {
    int idx = blockIdx.x * 256 + threadIdx.x;  // 2*B*E
    int which = idx >> 13;
    int r2 = idx & 8191;
    int b = r2 >> 9, e = r2 & 511;
    const float* W = in_proj_W + (size_t)(1 + which) * E_ * E_ + (size_t)e * E_;
    float s = in_proj_b[(1 + which) * E_ + e];
    const float* a = g_static_token + b * E_;
#pragma unroll 8
    for (int i = 0; i < E_; i++) s += a[i] * W[i];
    float* dst = which ? g_v : g_k;
    dst[((size_t)(b * S1_ + S_)) * E_ + e] = s;
}

// ---------------- big GEMMs ----------------
__global__ void __launch_bounds__(256) kv_gemm(const float* __restrict__ dyn, int which) {
    __shared__ float AsT[4096], WsT[4096];
    int nb = blockIdx.x, mb = blockIdx.y;
    int tid = threadIdx.x, ty = tid >> 4, tx = tid & 15;
    const float* W = which ? g_Wv_dyn : g_Wk_dyn;
    const float* bias = which ? g_bv : g_bk;
    float* outp = which ? g_v : g_k;
    const float* Ag = dyn + (size_t)(mb * 64) * DD_;
    const float* Wg = W + (size_t)(nb * 64) * DD_;
    float4 acc[4] = {};
    for (int kc = 0; kc < DD_; kc += 64) {
        load_tileT_rm(AsT, Ag + kc, DD_);
        load_tileT_rm(WsT, Wg + kc, DD_);
        __syncthreads();
        mm_chunk(AsT, WsT, acc, ty << 2, tx << 2);
        __syncthreads();
    }
    int n0 = nb * 64 + (tx << 2);
    float4 bv4 = *reinterpret_cast<const float4*>(bias + n0);
#pragma unroll
    for (int i = 0; i < 4; i++) {
        int row = mb * 64 + (ty << 2) + i;
        int b = row >> 10, s = row & 1023;
        float4 r = acc[i];
        r.x += bv4.x; r.y += bv4.y; r.z += bv4.z; r.w += bv4.w;
        *reinterpret_cast<float4*>(outp + ((size_t)(b * S1_ + s)) * E_ + n0) = r;
    }
}

__global__ void __launch_bounds__(256) q_gemm(const float* __restrict__ x) {
    __shared__ float AsT[4096], WsT[4096];
    int nb = blockIdx.x, mb = blockIdx.y;
    int tid = threadIdx.x, ty = tid >> 4, tx = tid & 15;
    int row0 = mb * 64;
    int b = row0 >> 10, h0 = row0 & 1023;
    const float* Ag = x + (size_t)b * C_ * H_ + h0;  // element (m,k): + k*H + m
    const float* Wg = g_Wq_comb + (size_t)(nb * 64) * C_;
    float4 acc[4] = {};
    for (int kc = 0; kc < C_; kc += 64) {
        load_tileT_cm(AsT, Ag + (size_t)kc * H_, H_);
        load_tileT_rm(WsT, Wg + kc, C_);
        __syncthreads();
        mm_chunk(AsT, WsT, acc, ty << 2, tx << 2);
        __syncthreads();
    }
    int n0 = nb * 64 + (tx << 2);
    float4 bv4 = *reinterpret_cast<const float4*>(g_bq_comb + n0);
#pragma unroll
    for (int i = 0; i < 4; i++) {
        int row = row0 + (ty << 2) + i;
        float4 r = acc[i];
        r.x += bv4.x; r.y += bv4.y; r.z += bv4.z; r.w += bv4.w;
        *reinterpret_cast<float4*>(g_q + (size_t)row * E_ + n0) = r;
    }
}

__global__ void __launch_bounds__(256) out_gemm(const float* __restrict__ x,
                                                float* __restrict__ out) {
    __shared__ float AsT[4096], WsT[4096];
    int nb = blockIdx.x;  // h tile
    int mb = blockIdx.y;  // c tile
    int b = blockIdx.z;
    int tid = threadIdx.x, ty = tid >> 4, tx = tid & 15;
    const float* Ag = g_Wco + (size_t)(mb * 64) * E_;
    const float* Bg = g_ctx + ((size_t)b * H_ + nb * 64) * E_;
    float4 acc[4] = {};
    for (int kc = 0; kc < E_; kc += 64) {
        load_tileT_rm(AsT, Ag + kc, E_);
        load_tileT_rm(WsT, Bg + kc, E_);
        __syncthreads();
        mm_chunk(AsT, WsT, acc, ty << 2, tx << 2);
        __syncthreads();
    }
    int h0n = nb * 64 + (tx << 2);
#pragma unroll
    for (int i = 0; i < 4; i++) {
        int c = mb * 64 + (ty << 2) + i;
        float sc = 1.f + g_film[b * C_ + c];
        float bb = g_bco[c];
        size_t off = ((size_t)b * C_ + c) * H_ + h0n;
        float4 xv = *reinterpret_cast<const float4*>(x + off);
        float4 r;
        r.x = (xv.x + acc[i].x + bb) * sc;
        r.y = (xv.y + acc[i].y + bb) * sc;
        r.z = (xv.z + acc[i].z + bb) * sc;
        r.w = (xv.w + acc[i].w + bb) * sc;
        *reinterpret_cast<float4*>(out + off) = r;
    }
}

// ---------------- fused flash attention ----------------
static constexpr int ATTN_SMEM = (4 * 4096 + 192) * 4;

__global__ void __launch_bounds__(256) attn_kernel(const float* __restrict__ bias_table) {
    extern __shared__ float sm[];
    float* QsT = sm;
    float* KsT = sm + 4096;
    float* SsT = sm + 8192;
    float* Vs  = sm + 12288;  // natural [c][d]
    float* mrow = sm + 16384;
    float* lrow = sm + 16448;
    float* srow = sm + 16512;

    int qt = 15 - blockIdx.x;  // heavy tiles launch first
    int n = blockIdx.y, b = blockIdx.z;
    int h0 = qt << 6;
    int tid = threadIdx.x, ty = tid >> 4, tx = tid & 15;
    int r0 = ty << 2, c0 = tx << 2;

    load_tileT_rm(QsT, g_q + ((size_t)(b * H_ + h0)) * E_ + n * HD_, E_);
    if (tid < 64) { mrow[tid] = -1e30f; lrow[tid] = 0.f; }
    float4 o0 = {}, o1 = {}, o2 = {}, o3 = {};
    __syncthreads();

    for (int it = 0; it <= qt + 1; it++) {
        int kt = (it <= qt) ? it : 16;
        int k0 = kt << 6;
        int nvalid = (kt == 16) ? 1 : 64;
        const float* kg = g_k + ((size_t)(b * S1_ + k0)) * E_ + n * HD_;
        const float* vg = g_v + ((size_t)(b * S1_ + k0)) * E_ + n * HD_;
#pragma unroll
        for (int i = 0; i < 4; i++) {
            int fi = tid + (i << 8);
            int c = fi >> 4;
            int d4 = (fi & 15) << 2;
            float4 kv4 = make_float4(0.f, 0.f, 0.f, 0.f);
            float4 vv4 = make_float4(0.f, 0.f, 0.f, 0.f);
            if (c < nvalid) {
                kv4 = *reinterpret_cast<const float4*>(kg + (size_t)c * E_ + d4);
                vv4 = *reinterpret_cast<const float4*>(vg + (size_t)c * E_ + d4);
            }
            KsT[swz(d4 + 0, c)] = kv4.x;
            KsT[swz(d4 + 1, c)] = kv4.y;
            KsT[swz(d4 + 2, c)] = kv4.z;
            KsT[swz(d4 + 3, c)] = kv4.w;
            *reinterpret_cast<float4*>(Vs + (c << 6) + d4) = vv4;
        }
        __syncthreads();

        float4 sa[4] = {};
        mm_chunk(QsT, KsT, sa, r0, c0);
        // store scores transposed: SsT[c][r]
        *reinterpret_cast<float4*>(SsT + swz4(c0 + 0, r0)) = make_float4(sa[0].x, sa[1].x, sa[2].x, sa[3].x);
        *reinterpret_cast<float4*>(SsT + swz4(c0 + 1, r0)) = make_float4(sa[0].y, sa[1].y, sa[2].y, sa[3].y);
        *reinterpret_cast<float4*>(SsT + swz4(c0 + 2, r0)) = make_float4(sa[0].z, sa[1].z, sa[2].z, sa[3].z);
        *reinterpret_cast<float4*>(SsT + swz4(c0 + 3, r0)) = make_float4(sa[0].w, sa[1].w, sa[2].w, sa[3].w);
        __syncthreads();

        // online softmax: 4 threads per row, 16 cols each
        {
            int r = tid >> 2, seg = tid & 3;
            int h = h0 + r;
            float vals[16];
            float mloc = -1e30f;
#pragma unroll
            for (int j = 0; j < 16; j++) {
                int c = (seg << 4) + j;
                int kk = k0 + c;
                float val = -1e30f;
                if (kk < S1_ && !((kk < S_) && (kk > h))) {
                    val = SsT[swz(c, r)] * 0.125f + __ldg(bias_table + (h - kk + RELM - 1));
                }
                vals[j] = val;
                mloc = fmaxf(mloc, val);
            }
            mloc = fmaxf(mloc, __shfl_xor_sync(0xffffffffu, mloc, 1));
            mloc = fmaxf(mloc, __shfl_xor_sync(0xffffffffu, mloc, 2));
            float mold = mrow[r];
            float mnew = fmaxf(mold, mloc);
            float suml = 0.f;
#pragma unroll
            for (int j = 0; j < 16; j++) {
                int c = (seg << 4) + j;
                float p = __expf(vals[j] - mnew);
                suml += p;
                SsT[swz(c, r)] = p;
            }
            suml += __shfl_xor_sync(0xffffffffu, suml, 1);
            suml += __shfl_xor_sync(0xffffffffu, suml, 2);
            if (seg == 0) {
                float scl = __expf(mold - mnew);
                srow[r] = scl;
                lrow[r] = lrow[r] * scl + suml;
                mrow[r] = mnew;
            }
        }
        __syncthreads();

        // rescale O, accumulate P @ V
        {
            float sA = srow[r0 + 0], sB = srow[r0 + 1], sC = srow[r0 + 2], sD = srow[r0 + 3];
            o0.x *= sA; o0.y *= sA; o0.z *= sA; o0.w *= sA;
            o1.x *= sB; o1.y *= sB; o1.z *= sB; o1.w *= sB;
            o2.x *= sC; o2.y *= sC; o2.z *= sC; o2.w *= sC;
            o3.x *= sD; o3.y *= sD; o3.z *= sD; o3.w *= sD;
#pragma unroll 8
            for (int c = 0; c < 64; c++) {
                float4 p = *reinterpret_cast<const float4*>(SsT + swz4(c, r0));
                float4 vv = *reinterpret_cast<const float4*>(Vs + (c << 6) + c0);
                o0.x += p.x * vv.x; o0.y += p.x * vv.y; o0.z += p.x * vv.z; o0.w += p.x * vv.w;
                o1.x += p.y * vv.x; o1.y += p.y * vv.y; o1.z += p.y * vv.z; o1.w += p.y * vv.w;
                o2.x += p.z * vv.x; o2.y += p.z * vv.y; o2.z += p.z * vv.z; o2.w += p.z * vv.w;
                o3.x += p.w * vv.x; o3.y += p.w * vv.y; o3.z += p.w * vv.z; o3.w += p.w * vv.w;
            }
        }
        __syncthreads();
    }

    float i0 = 1.f / lrow[r0 + 0];
    float i1 = 1.f / lrow[r0 + 1];
    float i2 = 1.f / lrow[r0 + 2];
    float i3 = 1.f / lrow[r0 + 3];
    float* cp = g_ctx + ((size_t)(b * H_ + h0 + r0)) * E_ + n * HD_ + c0;
    float4 w0 = make_float4(o0.x * i0, o0.y * i0, o0.z * i0, o0.w * i0);
    float4 w1 = make_float4(o1.x * i1, o1.y * i1, o1.z * i1, o1.w * i1);
    float4 w2 = make_float4(o2.x * i2, o2.y * i2, o2.z * i2, o2.w * i2);
    float4 w3 = make_float4(o3.x * i3, o3.y * i3, o3.z * i3, o3.w * i3);
    *reinterpret_cast<float4*>(cp + 0 * E_) = w0;
    *reinterpret_cast<float4*>(cp + 1 * E_) = w1;
    *reinterpret_cast<float4*>(cp + 2 * E_) = w2;
    *reinterpret_cast<float4*>(cp + 3 * E_) = w3;
}

// ---------------- launch ----------------
extern "C" void kernel_launch(void* const* d_in, const int* in_sizes, int n_in,
                              void* d_out, int out_size) {
    const float* x         = (const float*)d_in[0];
    const float* dyn       = (const float*)d_in[1];
    const float* statin    = (const float*)d_in[2];
    const float* dyn_W     = (const float*)d_in[3];
    const float* dyn_b     = (const float*)d_in[4];
    const float* stat_W    = (const float*)d_in[5];
    const float* stat_b    = (const float*)d_in[6];
    const float* film_W1   = (const float*)d_in[7];
    const float* film_b1   = (const float*)d_in[8];
    const float* film_W2   = (const float*)d_in[9];
    const float* film_b2   = (const float*)d_in[10];
    const float* q_W       = (const float*)d_in[11];
    const float* q_b       = (const float*)d_in[12];
    const float* in_proj_W = (const float*)d_in[13];
    const float* in_proj_b = (const float*)d_in[14];
    const float* out_W     = (const float*)d_in[15];
    const float* out_b     = (const float*)d_in[16];
    const float* ctx_W     = (const float*)d_in[17];
    const float* ctx_b     = (const float*)d_in[18];
    const float* bias_tab  = (const float*)d_in[19];
    float* out = (float*)d_out;

    cudaFuncSetAttribute(attn_kernel, cudaFuncAttributeMaxDynamicSharedMemorySize, ATTN_SMEM);

    // conditioning path
    k_static<<<(B_ * E_) / 256, 256>>>(statin, stat_W, stat_b);
    k_hidden<<<(B_ * E_) / 256, 256>>>(film_W1, film_b1);
    k_film<<<(B_ * C_) / 256, 256>>>(film_W2, film_b2);

    // fused weight precompute
    comb_kernel<<<(E_ * C_) / 256, 256>>>(0, in_proj_W, q_W, C_, E_, E_, C_);
    comb_kernel<<<(E_ * DD_) / 256, 256>>>(1, in_proj_W + E_ * E_, dyn_W, DD_, E_, E_, DD_);
    comb_kernel<<<(E_ * DD_) / 256, 256>>>(2, in_proj_W + 2 * E_ * E_, dyn_W, DD_, E_, E_, DD_);
    comb_kernel<<<(C_ * E_) / 256, 256>>>(3, ctx_W, out_W, E_, E_, E_, E_);
    biasc_kernel<<<2, 256>>>(0, in_proj_W, E_, q_b, in_proj_b, E_);
    biasc_kernel<<<2, 256>>>(1, in_proj_W + E_ * E_, E_, dyn_b, in_proj_b + E_, E_);
    biasc_kernel<<<2, 256>>>(2, in_proj_W + 2 * E_ * E_, E_, dyn_b, in_proj_b + 2 * E_, E_);
    biasc_kernel<<<1, 256>>>(3, ctx_W, E_, out_b, ctx_b, E_);
    stat_kv_kernel<<<(2 * B_ * E_) / 256, 256>>>(in_proj_W, in_proj_b);

    // projections
    kv_gemm<<<dim3(8, 256), 256>>>(dyn, 0);
    kv_gemm<<<dim3(8, 256), 256>>>(dyn, 1);
    q_gemm<<<dim3(8, 256), 256>>>(x);

    // attention
    attn_kernel<<<dim3(16, NH_, B_), 256, ATTN_SMEM>>>(bias_tab);

    // output projection + residual + FiLM
    out_gemm<<<dim3(16, 4, 16), 256>>>(x, out);

    (void)in_sizes; (void)n_in; (void)out_size;
}

// round 9
// speedup vs baseline: 2.5796x; 2.5729x over previous
#include <cuda_runtime.h>
#include <cuda_bf16.h>
#include <math.h>
#include <stdint.h>

static constexpr int B_ = 16, C_ = 256, H_ = 1024, S_ = 1024, E_ = 512;
static constexpr int NH_ = 8, HD_ = 64, DD_ = 512, DS_ = 64;
static constexpr int S1_ = S_ + 1;
static constexpr int RELM = 2048;

// ---------------- device scratch (NEVER passed from host) ----------------
__device__ float g_static_token[B_ * E_];
__device__ float g_hidden[B_ * E_];
__device__ float g_film[B_ * C_];
__device__ float g_bq[E_], g_bk[E_], g_bv[E_], g_bco[C_];
__device__ __nv_bfloat16 g_q_bf[(size_t)B_ * H_ * E_];
__device__ __nv_bfloat16 g_k_bf[(size_t)B_ * S1_ * E_];
__device__ __nv_bfloat16 g_v_bf[(size_t)B_ * S1_ * E_];
__device__ __nv_bfloat16 g_ctx_bf[(size_t)B_ * H_ * E_];
__device__ __nv_bfloat16 g_dyn_bf[(size_t)B_ * S_ * DD_];
__device__ __nv_bfloat16 g_xT[(size_t)B_ * H_ * C_];
__device__ __nv_bfloat16 g_Wq_bf[E_ * C_];
__device__ __nv_bfloat16 g_Wk_bf[E_ * DD_];
__device__ __nv_bfloat16 g_Wv_bf[E_ * DD_];
__device__ __nv_bfloat16 g_Wco_bf[C_ * E_];

// ---------------- HMMA helpers ----------------
__device__ __forceinline__ void mma16816(float* c, const uint32_t a[4], uint32_t b0, uint32_t b1) {
    asm volatile("mma.sync.aligned.m16n8k16.row.col.f32.bf16.bf16.f32 "
                 "{%0,%1,%2,%3},{%4,%5,%6,%7},{%8,%9},{%0,%1,%2,%3};"
                 : "+f"(c[0]), "+f"(c[1]), "+f"(c[2]), "+f"(c[3])
                 : "r"(a[0]), "r"(a[1]), "r"(a[2]), "r"(a[3]), "r"(b0), "r"(b1));
}
__device__ __forceinline__ uint32_t ld32bf(const __nv_bfloat16* p) {
    return *reinterpret_cast<const uint32_t*>(p);
}
__device__ __forceinline__ uint32_t pack_bf2(float a, float b) {
    __nv_bfloat162 h = __floats2bfloat162_rn(a, b);
    return *reinterpret_cast<uint32_t*>(&h);
}

// ---------------- HMMA GEMM: O[M,N] = A[M,K] @ W[N,K]^T ----------------
// modes: 0=q (bf16), 1=k (bf16), 2=v (bf16), 3=out (f32 + residual + film)
static constexpr int PAD = 56;
__global__ void __launch_bounds__(256) hmma_gemm(int mode,
                                                 const float* __restrict__ xin,
                                                 float* __restrict__ outf) {
    __shared__ __nv_bfloat16 sA[128 * PAD];
    __shared__ __nv_bfloat16 sB[128 * PAD];
    const __nv_bfloat16* A = (mode == 0) ? g_xT : (mode == 3) ? g_ctx_bf : g_dyn_bf;
    const __nv_bfloat16* W = (mode == 0) ? g_Wq_bf : (mode == 1) ? g_Wk_bf
                           : (mode == 2) ? g_Wv_bf : g_Wco_bf;
    int lda = (mode == 0) ? C_ : DD_;
    int tid = threadIdx.x, warp = tid >> 5, lane = tid & 31;
    int g = lane >> 2, c2 = (lane & 3) * 2;
    int wm = warp & 3, wn = warp >> 2;  // 4x2 warp grid, warp tile 32x64
    int n0 = blockIdx.x * 128, m0 = blockIdx.y * 128;

    float acc[2][8][4];
#pragma unroll
    for (int i = 0; i < 2; i++)
#pragma unroll
        for (int j = 0; j < 8; j++)
#pragma unroll
            for (int t = 0; t < 4; t++) acc[i][j][t] = 0.f;

    for (int kc = 0; kc < lda; kc += 32) {
#pragma unroll
        for (int i = 0; i < 2; i++) {
            int idx = tid + i * 256;
            int row = idx >> 2, seg = idx & 3;
            *reinterpret_cast<uint4*>(&sA[row * PAD + seg * 8]) =
                *reinterpret_cast<const uint4*>(&A[(size_t)(m0 + row) * lda + kc + seg * 8]);
            *reinterpret_cast<uint4*>(&sB[row * PAD + seg * 8]) =
                *reinterpret_cast<const uint4*>(&W[(size_t)(n0 + row) * lda + kc + seg * 8]);
        }
        __syncthreads();
#pragma unroll
        for (int ks = 0; ks < 2; ks++) {
            int k0 = ks * 16;
            uint32_t af[2][4];
#pragma unroll
            for (int mf = 0; mf < 2; mf++) {
                const __nv_bfloat16* ap = &sA[(wm * 32 + mf * 16 + g) * PAD + k0 + c2];
                af[mf][0] = ld32bf(ap);
                af[mf][1] = ld32bf(ap + 8 * PAD);
                af[mf][2] = ld32bf(ap + 8);
                af[mf][3] = ld32bf(ap + 8 * PAD + 8);
            }
#pragma unroll
            for (int nf = 0; nf < 8; nf++) {
                const __nv_bfloat16* bp = &sB[(wn * 64 + nf * 8 + g) * PAD + k0 + c2];
                uint32_t b0 = ld32bf(bp), b1 = ld32bf(bp + 8);
                mma16816(acc[0][nf], af[0], b0, b1);
                mma16816(acc[1][nf], af[1], b0, b1);
            }
        }
        __syncthreads();
    }

    const float* bias = (mode == 0) ? g_bq : (mode == 1) ? g_bk : (mode == 2) ? g_bv : g_bco;
    if (mode <= 2) {
#pragma unroll
        for (int mf = 0; mf < 2; mf++) {
            int r = m0 + wm * 32 + mf * 16 + g;
            __nv_bfloat16* d0;
            __nv_bfloat16* d1;
            if (mode == 0) {
                d0 = g_q_bf + (size_t)r * E_;
                d1 = g_q_bf + (size_t)(r + 8) * E_;
            } else {
                __nv_bfloat16* base = (mode == 1) ? g_k_bf : g_v_bf;
                int b0r = r >> 10, s0r = r & 1023;
                int b1r = (r + 8) >> 10, s1r = (r + 8) & 1023;
                d0 = base + ((size_t)(b0r * S1_ + s0r)) * E_;
                d1 = base + ((size_t)(b1r * S1_ + s1r)) * E_;
            }
#pragma unroll
            for (int nf = 0; nf < 8; nf++) {
                int cc = n0 + wn * 64 + nf * 8 + c2;
                float bb0 = bias[cc], bb1 = bias[cc + 1];
                *reinterpret_cast<uint32_t*>(d0 + cc) = pack_bf2(acc[mf][nf][0] + bb0, acc[mf][nf][1] + bb1);
                *reinterpret_cast<uint32_t*>(d1 + cc) = pack_bf2(acc[mf][nf][2] + bb0, acc[mf][nf][3] + bb1);
            }
        }
    } else {
#pragma unroll
        for (int mf = 0; mf < 2; mf++) {
            int r = m0 + wm * 32 + mf * 16 + g;
            int bb = r >> 10;
            int h0v = r & 1023;
#pragma unroll
            for (int nf = 0; nf < 8; nf++) {
                int cc = n0 + wn * 64 + nf * 8 + c2;
#pragma unroll
                for (int u = 0; u < 2; u++) {
                    int c = cc + u;
                    float sc = 1.f + g_film[bb * C_ + c];
                    float bco = bias[c];
                    size_t o0 = ((size_t)bb * C_ + c) * H_ + h0v;
                    size_t o1 = o0 + 8;
                    outf[o0] = (xin[o0] + acc[mf][nf][u] + bco) * sc;
                    outf[o1] = (xin[o1] + acc[mf][nf][2 + u] + bco) * sc;
                }
            }
        }
    }
}

// ---------------- HMMA flash attention ----------------
static constexpr int APAD = 72;
__global__ void __launch_bounds__(128) attn_hmma(const float* __restrict__ bias_table) {
    __shared__ __nv_bfloat16 smK[64 * APAD];
    __shared__ __nv_bfloat16 smVT[64 * APAD];
    int qt = 15 - blockIdx.x;
    int n = blockIdx.y, b = blockIdx.z;
    int h0 = qt << 6;
    int tid = threadIdx.x, warp = tid >> 5, lane = tid & 31;
    int g = lane >> 2, c2 = (lane & 3) * 2;
    int hg = h0 + warp * 16 + g, hh = hg + 8;

    uint32_t qa[4][4];
    {
        const __nv_bfloat16* qg = g_q_bf + ((size_t)(b * H_) + hg) * E_ + n * HD_;
        const __nv_bfloat16* qh = qg + 8 * E_;
#pragma unroll
        for (int j = 0; j < 4; j++) {
            qa[j][0] = ld32bf(qg + j * 16 + c2);
            qa[j][1] = ld32bf(qh + j * 16 + c2);
            qa[j][2] = ld32bf(qg + j * 16 + c2 + 8);
            qa[j][3] = ld32bf(qh + j * 16 + c2 + 8);
        }
    }

    float m0 = -1e30f, m1 = -1e30f, l0 = 0.f, l1 = 0.f;
    float oa[8][4];
#pragma unroll
    for (int j = 0; j < 8; j++)
#pragma unroll
        for (int t = 0; t < 4; t++) oa[j][t] = 0.f;

    for (int it = 0; it <= qt + 1; it++) {
        bool last = (it > qt);
        int k0 = last ? S_ : (it << 6);

        if (!last) {
            const __nv_bfloat16* kg = g_k_bf + ((size_t)(b * S1_ + k0)) * E_ + n * HD_;
            const __nv_bfloat16* vg = g_v_bf + ((size_t)(b * S1_ + k0)) * E_ + n * HD_;
#pragma unroll
            for (int i = 0; i < 4; i++) {
                int idx = tid + i * 128;
                int row = idx >> 3, seg = idx & 7;
                *reinterpret_cast<uint4*>(&smK[row * APAD + seg * 8]) =
                    *reinterpret_cast<const uint4*>(kg + (size_t)row * E_ + seg * 8);
            }
            {
                int key = tid & 63, dj = (tid >> 6) * 32;
#pragma unroll
                for (int j = 0; j < 4; j++) {
                    uint4 u = *reinterpret_cast<const uint4*>(vg + (size_t)key * E_ + dj + j * 8);
                    const __nv_bfloat16* e = reinterpret_cast<const __nv_bfloat16*>(&u);
#pragma unroll
                    for (int t = 0; t < 8; t++) smVT[(dj + j * 8 + t) * APAD + key] = e[t];
                }
            }
        } else {
#pragma unroll
            for (int i = 0; i < 5; i++) {
                int idx = tid + i * 128;
                if (idx < 64 * APAD / 8) {
                    *reinterpret_cast<uint4*>(&smK[idx * 8]) = make_uint4(0, 0, 0, 0);
                    *reinterpret_cast<uint4*>(&smVT[idx * 8]) = make_uint4(0, 0, 0, 0);
                }
            }
            __syncthreads();
            if (tid < 64) {
                smK[0 * APAD + tid] = g_k_bf[((size_t)(b * S1_ + S_)) * E_ + n * HD_ + tid];
                smVT[tid * APAD + 0] = g_v_bf[((size_t)(b * S1_ + S_)) * E_ + n * HD_ + tid];
            }
        }
        __syncthreads();

        float sc[8][4];
#pragma unroll
        for (int j = 0; j < 8; j++)
#pragma unroll
            for (int t = 0; t < 4; t++) sc[j][t] = 0.f;
#pragma unroll
        for (int j = 0; j < 4; j++) {
#pragma unroll
            for (int nf = 0; nf < 8; nf++) {
                const __nv_bfloat16* bp = &smK[(nf * 8 + g) * APAD + j * 16 + c2];
                mma16816(sc[nf], qa[j], ld32bf(bp), ld32bf(bp + 8));
            }
        }

        float vg16[16], vh16[16];
        float mlg = -1e30f, mlh = -1e30f;
#pragma unroll
        for (int nf = 0; nf < 8; nf++) {
#pragma unroll
            for (int u = 0; u < 2; u++) {
                int col = nf * 8 + c2 + u;
                int kk = k0 + col;
                bool inb = (kk < S1_);
                bool okg = inb && (kk >= S_ || kk <= hg);
                bool okh = inb && (kk >= S_ || kk <= hh);
                float vgv = okg ? sc[nf][u] * 0.125f + __ldg(bias_table + (hg - kk + RELM - 1)) : -1e30f;
                float vhv = okh ? sc[nf][2 + u] * 0.125f + __ldg(bias_table + (hh - kk + RELM - 1)) : -1e30f;
                vg16[nf * 2 + u] = vgv;
                vh16[nf * 2 + u] = vhv;
                mlg = fmaxf(mlg, vgv);
                mlh = fmaxf(mlh, vhv);
            }
        }
        mlg = fmaxf(mlg, __shfl_xor_sync(0xffffffffu, mlg, 1));
        mlg = fmaxf(mlg, __shfl_xor_sync(0xffffffffu, mlg, 2));
        mlh = fmaxf(mlh, __shfl_xor_sync(0xffffffffu, mlh, 1));
        mlh = fmaxf(mlh, __shfl_xor_sync(0xffffffffu, mlh, 2));
        float mng = fmaxf(m0, mlg), mnh = fmaxf(m1, mlh);
        float cg = __expf(m0 - mng), ch = __expf(m1 - mnh);
        uint32_t pkg[8], pkh[8];
        float sg = 0.f, sh = 0.f;
#pragma unroll
        for (int nf = 0; nf < 8; nf++) {
            float p0 = __expf(vg16[nf * 2 + 0] - mng);
            float p1 = __expf(vg16[nf * 2 + 1] - mng);
            float p2 = __expf(vh16[nf * 2 + 0] - mnh);
            float p3 = __expf(vh16[nf * 2 + 1] - mnh);
            sg += p0 + p1;
            sh += p2 + p3;
            pkg[nf] = pack_bf2(p0, p1);
            pkh[nf] = pack_bf2(p2, p3);
        }
        sg += __shfl_xor_sync(0xffffffffu, sg, 1);
        sg += __shfl_xor_sync(0xffffffffu, sg, 2);
        sh += __shfl_xor_sync(0xffffffffu, sh, 1);
        sh += __shfl_xor_sync(0xffffffffu, sh, 2);
        l0 = l0 * cg + sg;
        l1 = l1 * ch + sh;
        m0 = mng;
        m1 = mnh;
#pragma unroll
        for (int nf = 0; nf < 8; nf++) {
            oa[nf][0] *= cg; oa[nf][1] *= cg;
            oa[nf][2] *= ch; oa[nf][3] *= ch;
        }

#pragma unroll
        for (int j = 0; j < 4; j++) {
            uint32_t pa[4] = {pkg[2 * j], pkh[2 * j], pkg[2 * j + 1], pkh[2 * j + 1]};
#pragma unroll
            for (int nf = 0; nf < 8; nf++) {
                const __nv_bfloat16* bp = &smVT[(nf * 8 + g) * APAD + j * 16 + c2];
                mma16816(oa[nf], pa, ld32bf(bp), ld32bf(bp + 8));
            }
        }
        __syncthreads();
    }

    float i0 = 1.f / l0, i1 = 1.f / l1;
    __nv_bfloat16* d0 = g_ctx_bf + ((size_t)(b * H_) + hg) * E_ + n * HD_;
    __nv_bfloat16* d1 = d0 + 8 * E_;
#pragma unroll
    for (int nf = 0; nf < 8; nf++) {
        int d = nf * 8 + c2;
        *reinterpret_cast<uint32_t*>(d0 + d) = pack_bf2(oa[nf][0] * i0, oa[nf][1] * i0);
        *reinterpret_cast<uint32_t*>(d1 + d) = pack_bf2(oa[nf][2] * i1, oa[nf][3] * i1);
    }
}

// ---------------- SIMT fp32 64x64 tile (weight combos) ----------------
__device__ __forceinline__ int swz(int r, int c) {
    return (r << 6) + (((c & 60) ^ ((r & 15) << 2)) | (c & 3));
}
__device__ __forceinline__ int swz4(int r, int c4) { return (r << 6) + (c4 ^ ((r & 15) << 2)); }
__device__ __forceinline__ void load_tileT_rm(float* sm, const float* g, int ld) {
    int tid = threadIdx.x;
#pragma unroll
    for (int i = 0; i < 4; i++) {
        int fi = tid + (i << 8);
        int m = fi >> 4, k4 = (fi & 15) << 2;
        float4 v = *reinterpret_cast<const float4*>(g + (size_t)m * ld + k4);
        sm[swz(k4 + 0, m)] = v.x; sm[swz(k4 + 1, m)] = v.y;
        sm[swz(k4 + 2, m)] = v.z; sm[swz(k4 + 3, m)] = v.w;
    }
}
__device__ __forceinline__ void load_tileT_cm(float* sm, const float* g, int ldk) {
    int tid = threadIdx.x;
#pragma unroll
    for (int i = 0; i < 4; i++) {
        int fi = tid + (i << 8);
        int k = fi >> 4, m4 = (fi & 15) << 2;
        float4 v = *reinterpret_cast<const float4*>(g + (size_t)k * ldk + m4);
        *reinterpret_cast<float4*>(sm + swz4(k, m4)) = v;
    }
}
__device__ __forceinline__ void mm_chunk(const float* __restrict__ AsT, const float* __restrict__ WsT,
                                         float4 acc[4], int m0, int n0) {
#pragma unroll 8
    for (int k = 0; k < 64; k++) {
        float4 a = *reinterpret_cast<const float4*>(AsT + swz4(k, m0));
        float4 w = *reinterpret_cast<const float4*>(WsT + swz4(k, n0));
        acc[0].x += a.x * w.x; acc[0].y += a.x * w.y; acc[0].z += a.x * w.z; acc[0].w += a.x * w.w;
        acc[1].x += a.y * w.x; acc[1].y += a.y * w.y; acc[1].z += a.y * w.z; acc[1].w += a.y * w.w;
        acc[2].x += a.z * w.x; acc[2].y += a.z * w.y; acc[2].z += a.z * w.z; acc[2].w += a.z * w.w;
        acc[3].x += a.w * w.x; acc[3].y += a.w * w.y; acc[3].z += a.w * w.z; acc[3].w += a.w * w.w;
    }
}
// O[n][m] = sum_k L[n][k]*R[k][m], bf16 out selected by target; grid (M/64, N/64)
__global__ void __launch_bounds__(256) comb_tiled(int target, const float* __restrict__ L,
                                                  const float* __restrict__ R, int M, int K, int ldL, int ldR) {
    __shared__ float AsT[4096], WsT[4096];
    int mb = blockIdx.x, nb = blockIdx.y;
    int tid = threadIdx.x, ty = tid >> 4, tx = tid & 15;
    const float* Lg = L + (size_t)(nb * 64) * ldL;
    const float* Rg = R + mb * 64;
    float4 acc[4] = {};
    for (int kc = 0; kc < K; kc += 64) {
        load_tileT_rm(AsT, Lg + kc, ldL);
        load_tileT_cm(WsT, Rg + (size_t)kc * ldR, ldR);
        __syncthreads();
        mm_chunk(AsT, WsT, acc, ty << 2, tx << 2);
        __syncthreads();
    }
    __nv_bfloat16* O = (target == 0) ? g_Wq_bf : (target == 1) ? g_Wk_bf
                     : (target == 2) ? g_Wv_bf : g_Wco_bf;
    int m0 = mb * 64 + (tx << 2);
#pragma unroll
    for (int i = 0; i < 4; i++) {
        int nn = nb * 64 + (ty << 2) + i;
        *reinterpret_cast<uint2*>(O + (size_t)nn * M + m0) =
            make_uint2(pack_bf2(acc[i].x, acc[i].y), pack_bf2(acc[i].z, acc[i].w));
    }
}

// ---------------- small conditioning kernels ----------------
__global__ void __launch_bounds__(256) k_static(const float* __restrict__ st, const float* __restrict__ stat_W,
                                                const float* __restrict__ stat_b) {
    int idx = blockIdx.x * 256 + threadIdx.x;
    int b = idx >> 9, e = idx & 511;
    float s = stat_b[e];
    const float* a = st + b * DS_;
    const float* w = stat_W + e * DS_;
#pragma unroll 8
    for (int d = 0; d < DS_; d++) s += a[d] * w[d];
    g_static_token[idx] = s;
}
__global__ void __launch_bounds__(256) k_hidden(const float* __restrict__ W1, const float* __restrict__ b1) {
    int idx = blockIdx.x * 256 + threadIdx.x;
    int b = idx >> 9, e = idx & 511;
    float s = b1[e];
    const float* a = g_static_token + b * E_;
    const float* w = W1 + (size_t)e * E_;
#pragma unroll 8
    for (int i = 0; i < E_; i++) s += a[i] * w[i];
    g_hidden[idx] = s >= 0.f ? s : 0.1f * s;
}
__global__ void __launch_bounds__(256) k_film(const float* __restrict__ W2, const float* __restrict__ b2) {
    int idx = blockIdx.x * 256 + threadIdx.x;
    int b = idx >> 8, c = idx & 255;
    float s = b2[c];
    const float* a = g_hidden + b * E_;
    const float* w = W2 + (size_t)c * E_;
#pragma unroll 8
    for (int i = 0; i < E_; i++) s += a[i] * w[i];
    g_film[idx] = tanhf(s);
}
__global__ void __launch_bounds__(256) biasc_kernel(int target, const float* __restrict__ L, int ldL,
                                                    const float* __restrict__ vec, const float* __restrict__ addv, int K) {
    int n = blockIdx.x * 256 + threadIdx.x;
    float s = addv[n];
#pragma unroll 8
    for (int k = 0; k < K; k++) s += L[(size_t)n * ldL + k] * vec[k];
    float* o = (target == 0) ? g_bq : (target == 1) ? g_bk : (target == 2) ? g_bv : g_bco;
    o[n] = s;
}
__global__ void __launch_bounds__(256) stat_kv_kernel(const float* __restrict__ in_proj_W,
                                                      const float* __restrict__ in_proj_b) {
    int idx = blockIdx.x * 256 + threadIdx.x;  // 2*B*E
    int which = idx >> 13;
    int r2 = idx & 8191;
    int b = r2 >> 9, e = r2 & 511;
    const float* W = in_proj_W + (size_t)(1 + which) * E_ * E_ + (size_t)e * E_;
    float s = in_proj_b[(1 + which) * E_ + e];
    const float* a = g_static_token + b * E_;
#pragma unroll 8
    for (int i = 0; i < E_; i++) s += a[i] * W[i];
    __nv_bfloat16* dst = which ? g_v_bf : g_k_bf;
    dst[((size_t)(b * S1_ + S_)) * E_ + e] = __float2bfloat16(s);
}

// ---------------- converts (outputs selected internally) ----------------
__global__ void __launch_bounds__(256) cvt_dyn_kernel(const float* __restrict__ in, int n4) {
    int i = blockIdx.x * 256 + threadIdx.x;
    if (i < n4) {
        float4 v = reinterpret_cast<const float4*>(in)[i];
        reinterpret_cast<uint2*>(g_dyn_bf)[i] = make_uint2(pack_bf2(v.x, v.y), pack_bf2(v.z, v.w));
    }
}
__global__ void __launch_bounds__(256) xT_kernel(const float* __restrict__ x) {
    __shared__ float t[32][33];
    int h0 = blockIdx.x * 32, c0 = blockIdx.y * 32, b = blockIdx.z;
    int tx = threadIdx.x & 31, ty = threadIdx.x >> 5;
#pragma unroll
    for (int i = 0; i < 4; i++)
        t[ty + 8 * i][tx] = x[((size_t)b * C_ + c0 + ty + 8 * i) * H_ + h0 + tx];
    __syncthreads();
#pragma unroll
    for (int i = 0; i < 4; i++)
        g_xT[((size_t)b * H_ + h0 + ty + 8 * i) * C_ + c0 + tx] = __float2bfloat16(t[tx][ty + 8 * i]);
}

// ---------------- launch ----------------
extern "C" void kernel_launch(void* const* d_in, const int* in_sizes, int n_in,
                              void* d_out, int out_size) {
    const float* x         = (const float*)d_in[0];
    const float* dyn       = (const float*)d_in[1];
    const float* statin    = (const float*)d_in[2];
    const float* dyn_W     = (const float*)d_in[3];
    const float* dyn_b     = (const float*)d_in[4];
    const float* stat_W    = (const float*)d_in[5];
    const float* stat_b    = (const float*)d_in[6];
    const float* film_W1   = (const float*)d_in[7];
    const float* film_b1   = (const float*)d_in[8];
    const float* film_W2   = (const float*)d_in[9];
    const float* film_b2   = (const float*)d_in[10];
    const float* q_W       = (const float*)d_in[11];
    const float* q_b       = (const float*)d_in[12];
    const float* in_proj_W = (const float*)d_in[13];
    const float* in_proj_b = (const float*)d_in[14];
    const float* out_W     = (const float*)d_in[15];
    const float* out_b     = (const float*)d_in[16];
    const float* ctx_W     = (const float*)d_in[17];
    const float* ctx_b     = (const float*)d_in[18];
    const float* bias_tab  = (const float*)d_in[19];
    float* out = (float*)d_out;

    // input conversions (globals referenced ONLY device-side)
    cvt_dyn_kernel<<<(B_ * S_ * DD_ / 4 + 255) / 256, 256>>>(dyn, B_ * S_ * DD_ / 4);
    xT_kernel<<<dim3(32, 8, 16), 256>>>(x);

    // conditioning path
    k_static<<<(B_ * E_) / 256, 256>>>(statin, stat_W, stat_b);
    k_hidden<<<(B_ * E_) / 256, 256>>>(film_W1, film_b1);
    k_film<<<(B_ * C_) / 256, 256>>>(film_W2, film_b2);

    // fused weight precompute (bf16 outputs, selected device-side)
    comb_tiled<<<dim3(4, 8), 256>>>(0, in_proj_W, q_W, C_, E_, E_, C_);
    comb_tiled<<<dim3(8, 8), 256>>>(1, in_proj_W + E_ * E_, dyn_W, DD_, E_, E_, DD_);
    comb_tiled<<<dim3(8, 8), 256>>>(2, in_proj_W + 2 * E_ * E_, dyn_W, DD_, E_, E_, DD_);
    comb_tiled<<<dim3(8, 4), 256>>>(3, ctx_W, out_W, E_, E_, E_, E_);
    biasc_kernel<<<2, 256>>>(0, in_proj_W, E_, q_b, in_proj_b, E_);
    biasc_kernel<<<2, 256>>>(1, in_proj_W + E_ * E_, E_, dyn_b, in_proj_b + E_, E_);
    biasc_kernel<<<2, 256>>>(2, in_proj_W + 2 * E_ * E_, E_, dyn_b, in_proj_b + 2 * E_, E_);
    biasc_kernel<<<1, 256>>>(3, ctx_W, E_, out_b, ctx_b, E_);
    stat_kv_kernel<<<(2 * B_ * E_) / 256, 256>>>(in_proj_W, in_proj_b);

    // HMMA projections (A/W selected device-side by mode)
    hmma_gemm<<<dim3(4, 128), 256>>>(0, nullptr, nullptr);
    hmma_gemm<<<dim3(4, 128), 256>>>(1, nullptr, nullptr);
    hmma_gemm<<<dim3(4, 128), 256>>>(2, nullptr, nullptr);

    // HMMA flash attention
    attn_hmma<<<dim3(16, NH_, B_), 128>>>(bias_tab);

    // output projection + residual + FiLM
    hmma_gemm<<<dim3(2, 128), 256>>>(3, x, out);

    (void)in_sizes; (void)n_in; (void)out_size;
}

// round 10
// speedup vs baseline: 4.9533x; 1.9202x over previous
#include <cuda_runtime.h>
#include <cuda_bf16.h>
#include <math.h>
#include <stdint.h>

static constexpr int B_ = 16, C_ = 256, H_ = 1024, S_ = 1024, E_ = 512;
static constexpr int NH_ = 8, HD_ = 64, DD_ = 512, DS_ = 64;
static constexpr int S1_ = S_ + 1;
static constexpr int RELM = 2048;

// ---------------- device scratch (NEVER passed from host) ----------------
__device__ float g_static_token[B_ * E_];
__device__ float g_hidden[B_ * E_];
__device__ float g_film[B_ * C_];
__device__ float g_bq[E_], g_bk[E_], g_bv[E_], g_bco[C_];
__device__ __nv_bfloat16 g_q_bf[(size_t)B_ * H_ * E_];
__device__ __nv_bfloat16 g_k_bf[(size_t)B_ * S1_ * E_];
__device__ __nv_bfloat16 g_v_bf[(size_t)B_ * S1_ * E_];
__device__ __nv_bfloat16 g_ctx_bf[(size_t)B_ * H_ * E_];
__device__ __nv_bfloat16 g_dyn_bf[(size_t)B_ * S_ * DD_];
__device__ __nv_bfloat16 g_xT[(size_t)B_ * H_ * C_];
__device__ __nv_bfloat16 g_Wq_bf[E_ * C_];
__device__ __nv_bfloat16 g_Wk_bf[E_ * DD_];
__device__ __nv_bfloat16 g_Wv_bf[E_ * DD_];
__device__ __nv_bfloat16 g_Wco_bf[C_ * E_];

// ---------------- HMMA helpers ----------------
__device__ __forceinline__ void mma16816(float* c, const uint32_t a[4], uint32_t b0, uint32_t b1) {
    asm volatile("mma.sync.aligned.m16n8k16.row.col.f32.bf16.bf16.f32 "
                 "{%0,%1,%2,%3},{%4,%5,%6,%7},{%8,%9},{%0,%1,%2,%3};"
                 : "+f"(c[0]), "+f"(c[1]), "+f"(c[2]), "+f"(c[3])
                 : "r"(a[0]), "r"(a[1]), "r"(a[2]), "r"(a[3]), "r"(b0), "r"(b1));
}
__device__ __forceinline__ uint32_t ld32bf(const __nv_bfloat16* p) {
    return *reinterpret_cast<const uint32_t*>(p);
}
__device__ __forceinline__ uint32_t pack_bf2(float a, float b) {
    __nv_bfloat162 h = __floats2bfloat162_rn(a, b);
    return *reinterpret_cast<uint32_t*>(&h);
}

// ---------------- warp-reduction helpers ----------------
__device__ __forceinline__ float warp_dot512(const float* __restrict__ a,
                                             const float* __restrict__ w, int lane) {
    float s = 0.f;
#pragma unroll
    for (int i = 0; i < 4; i++) {
        float4 av = *reinterpret_cast<const float4*>(a + lane * 4 + i * 128);
        float4 wv = *reinterpret_cast<const float4*>(w + lane * 4 + i * 128);
        s += av.x * wv.x + av.y * wv.y + av.z * wv.z + av.w * wv.w;
    }
#pragma unroll
    for (int o = 16; o; o >>= 1) s += __shfl_xor_sync(0xffffffffu, s, o);
    return s;
}

// ---------------- HMMA GEMM: O[M,N] = A[M,K] @ W[N,K]^T ----------------
// mode_arg: -1 = qkv combined (mode=blockIdx.z), 3 = out (f32 + residual + film)
static constexpr int PAD = 56;
__global__ void __launch_bounds__(256) hmma_gemm(int mode_arg,
                                                 const float* __restrict__ xin,
                                                 float* __restrict__ outf) {
    __shared__ __nv_bfloat16 sA[128 * PAD];
    __shared__ __nv_bfloat16 sB[128 * PAD];
    int mode = (mode_arg >= 0) ? mode_arg : (int)blockIdx.z;
    const __nv_bfloat16* A = (mode == 0) ? g_xT : (mode == 3) ? g_ctx_bf : g_dyn_bf;
    const __nv_bfloat16* W = (mode == 0) ? g_Wq_bf : (mode == 1) ? g_Wk_bf
                           : (mode == 2) ? g_Wv_bf : g_Wco_bf;
    int lda = (mode == 0) ? C_ : DD_;
    int tid = threadIdx.x, warp = tid >> 5, lane = tid & 31;
    int g = lane >> 2, c2 = (lane & 3) * 2;
    int wm = warp & 3, wn = warp >> 2;  // 4x2 warp grid, warp tile 32x64
    int n0 = blockIdx.x * 128, m0 = blockIdx.y * 128;

    float acc[2][8][4];
#pragma unroll
    for (int i = 0; i < 2; i++)
#pragma unroll
        for (int j = 0; j < 8; j++)
#pragma unroll
            for (int t = 0; t < 4; t++) acc[i][j][t] = 0.f;

    for (int kc = 0; kc < lda; kc += 32) {
#pragma unroll
        for (int i = 0; i < 2; i++) {
            int idx = tid + i * 256;
            int row = idx >> 2, seg = idx & 3;
            *reinterpret_cast<uint4*>(&sA[row * PAD + seg * 8]) =
                *reinterpret_cast<const uint4*>(&A[(size_t)(m0 + row) * lda + kc + seg * 8]);
            *reinterpret_cast<uint4*>(&sB[row * PAD + seg * 8]) =
                *reinterpret_cast<const uint4*>(&W[(size_t)(n0 + row) * lda + kc + seg * 8]);
        }
        __syncthreads();
#pragma unroll
        for (int ks = 0; ks < 2; ks++) {
            int k0 = ks * 16;
            uint32_t af[2][4];
#pragma unroll
            for (int mf = 0; mf < 2; mf++) {
                const __nv_bfloat16* ap = &sA[(wm * 32 + mf * 16 + g) * PAD + k0 + c2];
                af[mf][0] = ld32bf(ap);
                af[mf][1] = ld32bf(ap + 8 * PAD);
                af[mf][2] = ld32bf(ap + 8);
                af[mf][3] = ld32bf(ap + 8 * PAD + 8);
            }
#pragma unroll
            for (int nf = 0; nf < 8; nf++) {
                const __nv_bfloat16* bp = &sB[(wn * 64 + nf * 8 + g) * PAD + k0 + c2];
                uint32_t b0 = ld32bf(bp), b1 = ld32bf(bp + 8);
                mma16816(acc[0][nf], af[0], b0, b1);
                mma16816(acc[1][nf], af[1], b0, b1);
            }
        }
        __syncthreads();
    }

    const float* bias = (mode == 0) ? g_bq : (mode == 1) ? g_bk : (mode == 2) ? g_bv : g_bco;
    if (mode <= 2) {
#pragma unroll
        for (int mf = 0; mf < 2; mf++) {
            int r = m0 + wm * 32 + mf * 16 + g;
            __nv_bfloat16* d0;
            __nv_bfloat16* d1;
            if (mode == 0) {
                d0 = g_q_bf + (size_t)r * E_;
                d1 = g_q_bf + (size_t)(r + 8) * E_;
            } else {
                __nv_bfloat16* base = (mode == 1) ? g_k_bf : g_v_bf;
                int b0r = r >> 10, s0r = r & 1023;
                int b1r = (r + 8) >> 10, s1r = (r + 8) & 1023;
                d0 = base + ((size_t)(b0r * S1_ + s0r)) * E_;
                d1 = base + ((size_t)(b1r * S1_ + s1r)) * E_;
            }
#pragma unroll
            for (int nf = 0; nf < 8; nf++) {
                int cc = n0 + wn * 64 + nf * 8 + c2;
                float bb0 = bias[cc], bb1 = bias[cc + 1];
                *reinterpret_cast<uint32_t*>(d0 + cc) = pack_bf2(acc[mf][nf][0] + bb0, acc[mf][nf][1] + bb1);
                *reinterpret_cast<uint32_t*>(d1 + cc) = pack_bf2(acc[mf][nf][2] + bb0, acc[mf][nf][3] + bb1);
            }
        }
    } else {
#pragma unroll
        for (int mf = 0; mf < 2; mf++) {
            int r = m0 + wm * 32 + mf * 16 + g;
            int bb = r >> 10;
            int h0v = r & 1023;
#pragma unroll
            for (int nf = 0; nf < 8; nf++) {
                int cc = n0 + wn * 64 + nf * 8 + c2;
#pragma unroll
                for (int u = 0; u < 2; u++) {
                    int c = cc + u;
                    float sc = 1.f + g_film[bb * C_ + c];
                    float bco = bias[c];
                    size_t o0 = ((size_t)bb * C_ + c) * H_ + h0v;
                    size_t o1 = o0 + 8;
                    outf[o0] = (xin[o0] + acc[mf][nf][u] + bco) * sc;
                    outf[o1] = (xin[o1] + acc[mf][nf][2 + u] + bco) * sc;
                }
            }
        }
    }
}

// ---------------- HMMA flash attention ----------------
static constexpr int APAD = 72;
__global__ void __launch_bounds__(128) attn_hmma(const float* __restrict__ bias_table) {
    __shared__ __nv_bfloat16 smK[64 * APAD];
    __shared__ __nv_bfloat16 smVT[64 * APAD];
    int qt = 15 - blockIdx.x;
    int n = blockIdx.y, b = blockIdx.z;
    int h0 = qt << 6;
    int tid = threadIdx.x, warp = tid >> 5, lane = tid & 31;
    int g = lane >> 2, c2 = (lane & 3) * 2;
    int hg = h0 + warp * 16 + g, hh = hg + 8;

    uint32_t qa[4][4];
    {
        const __nv_bfloat16* qg = g_q_bf + ((size_t)(b * H_) + hg) * E_ + n * HD_;
        const __nv_bfloat16* qh = qg + 8 * E_;
#pragma unroll
        for (int j = 0; j < 4; j++) {
            qa[j][0] = ld32bf(qg + j * 16 + c2);
            qa[j][1] = ld32bf(qh + j * 16 + c2);
            qa[j][2] = ld32bf(qg + j * 16 + c2 + 8);
            qa[j][3] = ld32bf(qh + j * 16 + c2 + 8);
        }
    }

    float m0 = -1e30f, m1 = -1e30f, l0 = 0.f, l1 = 0.f;
    float oa[8][4];
#pragma unroll
    for (int j = 0; j < 8; j++)
#pragma unroll
        for (int t = 0; t < 4; t++) oa[j][t] = 0.f;

    for (int it = 0; it <= qt + 1; it++) {
        bool last = (it > qt);
        int k0 = last ? S_ : (it << 6);

        if (!last) {
            const __nv_bfloat16* kg = g_k_bf + ((size_t)(b * S1_ + k0)) * E_ + n * HD_;
            const __nv_bfloat16* vg = g_v_bf + ((size_t)(b * S1_ + k0)) * E_ + n * HD_;
#pragma unroll
            for (int i = 0; i < 4; i++) {
                int idx = tid + i * 128;
                int row = idx >> 3, seg = idx & 7;
                *reinterpret_cast<uint4*>(&smK[row * APAD + seg * 8]) =
                    *reinterpret_cast<const uint4*>(kg + (size_t)row * E_ + seg * 8);
            }
            {
                int key = tid & 63, dj = (tid >> 6) * 32;
#pragma unroll
                for (int j = 0; j < 4; j++) {
                    uint4 u = *reinterpret_cast<const uint4*>(vg + (size_t)key * E_ + dj + j * 8);
                    const __nv_bfloat16* e = reinterpret_cast<const __nv_bfloat16*>(&u);
#pragma unroll
                    for (int t = 0; t < 8; t++) smVT[(dj + j * 8 + t) * APAD + key] = e[t];
                }
            }
        } else {
#pragma unroll
            for (int i = 0; i < 5; i++) {
                int idx = tid + i * 128;
                if (idx < 64 * APAD / 8) {
                    *reinterpret_cast<uint4*>(&smK[idx * 8]) = make_uint4(0, 0, 0, 0);
                    *reinterpret_cast<uint4*>(&smVT[idx * 8]) = make_uint4(0, 0, 0, 0);
                }
            }
            __syncthreads();
            if (tid < 64) {
                smK[0 * APAD + tid] = g_k_bf[((size_t)(b * S1_ + S_)) * E_ + n * HD_ + tid];
                smVT[tid * APAD + 0] = g_v_bf[((size_t)(b * S1_ + S_)) * E_ + n * HD_ + tid];
            }
        }
        __syncthreads();

        float sc[8][4];
#pragma unroll
        for (int j = 0; j < 8; j++)
#pragma unroll
            for (int t = 0; t < 4; t++) sc[j][t] = 0.f;
#pragma unroll
        for (int j = 0; j < 4; j++) {
#pragma unroll
            for (int nf = 0; nf < 8; nf++) {
                const __nv_bfloat16* bp = &smK[(nf * 8 + g) * APAD + j * 16 + c2];
                mma16816(sc[nf], qa[j], ld32bf(bp), ld32bf(bp + 8));
            }
        }

        float vg16[16], vh16[16];
        float mlg = -1e30f, mlh = -1e30f;
#pragma unroll
        for (int nf = 0; nf < 8; nf++) {
#pragma unroll
            for (int u = 0; u < 2; u++) {
                int col = nf * 8 + c2 + u;
                int kk = k0 + col;
                bool inb = (kk < S1_);
                bool okg = inb && (kk >= S_ || kk <= hg);
                bool okh = inb && (kk >= S_ || kk <= hh);
                float vgv = okg ? sc[nf][u] * 0.125f + __ldg(bias_table + (hg - kk + RELM - 1)) : -1e30f;
                float vhv = okh ? sc[nf][2 + u] * 0.125f + __ldg(bias_table + (hh - kk + RELM - 1)) : -1e30f;
                vg16[nf * 2 + u] = vgv;
                vh16[nf * 2 + u] = vhv;
                mlg = fmaxf(mlg, vgv);
                mlh = fmaxf(mlh, vhv);
            }
        }
        mlg = fmaxf(mlg, __shfl_xor_sync(0xffffffffu, mlg, 1));
        mlg = fmaxf(mlg, __shfl_xor_sync(0xffffffffu, mlg, 2));
        mlh = fmaxf(mlh, __shfl_xor_sync(0xffffffffu, mlh, 1));
        mlh = fmaxf(mlh, __shfl_xor_sync(0xffffffffu, mlh, 2));
        float mng = fmaxf(m0, mlg), mnh = fmaxf(m1, mlh);
        float cg = __expf(m0 - mng), ch = __expf(m1 - mnh);
        uint32_t pkg[8], pkh[8];
        float sg = 0.f, sh = 0.f;
#pragma unroll
        for (int nf = 0; nf < 8; nf++) {
            float p0 = __expf(vg16[nf * 2 + 0] - mng);
            float p1 = __expf(vg16[nf * 2 + 1] - mng);
            float p2 = __expf(vh16[nf * 2 + 0] - mnh);
            float p3 = __expf(vh16[nf * 2 + 1] - mnh);
            sg += p0 + p1;
            sh += p2 + p3;
            pkg[nf] = pack_bf2(p0, p1);
            pkh[nf] = pack_bf2(p2, p3);
        }
        sg += __shfl_xor_sync(0xffffffffu, sg, 1);
        sg += __shfl_xor_sync(0xffffffffu, sg, 2);
        sh += __shfl_xor_sync(0xffffffffu, sh, 1);
        sh += __shfl_xor_sync(0xffffffffu, sh, 2);
        l0 = l0 * cg + sg;
        l1 = l1 * ch + sh;
        m0 = mng;
        m1 = mnh;
#pragma unroll
        for (int nf = 0; nf < 8; nf++) {
            oa[nf][0] *= cg; oa[nf][1] *= cg;
            oa[nf][2] *= ch; oa[nf][3] *= ch;
        }

#pragma unroll
        for (int j = 0; j < 4; j++) {
            uint32_t pa[4] = {pkg[2 * j], pkh[2 * j], pkg[2 * j + 1], pkh[2 * j + 1]};
#pragma unroll
            for (int nf = 0; nf < 8; nf++) {
                const __nv_bfloat16* bp = &smVT[(nf * 8 + g) * APAD + j * 16 + c2];
                mma16816(oa[nf], pa, ld32bf(bp), ld32bf(bp + 8));
            }
        }
        __syncthreads();
    }

    float i0 = 1.f / l0, i1 = 1.f / l1;
    __nv_bfloat16* d0 = g_ctx_bf + ((size_t)(b * H_) + hg) * E_ + n * HD_;
    __nv_bfloat16* d1 = d0 + 8 * E_;
#pragma unroll
    for (int nf = 0; nf < 8; nf++) {
        int d = nf * 8 + c2;
        *reinterpret_cast<uint32_t*>(d0 + d) = pack_bf2(oa[nf][0] * i0, oa[nf][1] * i0);
        *reinterpret_cast<uint32_t*>(d1 + d) = pack_bf2(oa[nf][2] * i1, oa[nf][3] * i1);
    }
}

// ---------------- SIMT fp32 64x64 tile (weight combos) ----------------
__device__ __forceinline__ int swz(int r, int c) {
    return (r << 6) + (((c & 60) ^ ((r & 15) << 2)) | (c & 3));
}
__device__ __forceinline__ int swz4(int r, int c4) { return (r << 6) + (c4 ^ ((r & 15) << 2)); }
__device__ __forceinline__ void load_tileT_rm(float* sm, const float* g, int ld) {
    int tid = threadIdx.x;
#pragma unroll
    for (int i = 0; i < 4; i++) {
        int fi = tid + (i << 8);
        int m = fi >> 4, k4 = (fi & 15) << 2;
        float4 v = *reinterpret_cast<const float4*>(g + (size_t)m * ld + k4);
        sm[swz(k4 + 0, m)] = v.x; sm[swz(k4 + 1, m)] = v.y;
        sm[swz(k4 + 2, m)] = v.z; sm[swz(k4 + 3, m)] = v.w;
    }
}
__device__ __forceinline__ void load_tileT_cm(float* sm, const float* g, int ldk) {
    int tid = threadIdx.x;
#pragma unroll
    for (int i = 0; i < 4; i++) {
        int fi = tid + (i << 8);
        int k = fi >> 4, m4 = (fi & 15) << 2;
        float4 v = *reinterpret_cast<const float4*>(g + (size_t)k * ldk + m4);
        *reinterpret_cast<float4*>(sm + swz4(k, m4)) = v;
    }
}
__device__ __forceinline__ void mm_chunk(const float* __restrict__ AsT, const float* __restrict__ WsT,
                                         float4 acc[4], int m0, int n0) {
#pragma unroll 8
    for (int k = 0; k < 64; k++) {
        float4 a = *reinterpret_cast<const float4*>(AsT + swz4(k, m0));
        float4 w = *reinterpret_cast<const float4*>(WsT + swz4(k, n0));
        acc[0].x += a.x * w.x; acc[0].y += a.x * w.y; acc[0].z += a.x * w.z; acc[0].w += a.x * w.w;
        acc[1].x += a.y * w.x; acc[1].y += a.y * w.y; acc[1].z += a.y * w.z; acc[1].w += a.y * w.w;
        acc[2].x += a.z * w.x; acc[2].y += a.z * w.y; acc[2].z += a.z * w.z; acc[2].w += a.z * w.w;
        acc[3].x += a.w * w.x; acc[3].y += a.w * w.y; acc[3].z += a.w * w.z; acc[3].w += a.w * w.w;
    }
}
// O[n][m] = sum_k L[n][k]*R[k][m], bf16 out selected by target; grid (M/64, N/64)
__global__ void __launch_bounds__(256) comb_tiled(int target, const float* __restrict__ L,
                                                  const float* __restrict__ R, int M, int K, int ldL, int ldR) {
    __shared__ float AsT[4096], WsT[4096];
    int mb = blockIdx.x, nb = blockIdx.y;
    int tid = threadIdx.x, ty = tid >> 4, tx = tid & 15;
    const float* Lg = L + (size_t)(nb * 64) * ldL;
    const float* Rg = R + mb * 64;
    float4 acc[4] = {};
    for (int kc = 0; kc < K; kc += 64) {
        load_tileT_rm(AsT, Lg + kc, ldL);
        load_tileT_cm(WsT, Rg + (size_t)kc * ldR, ldR);
        __syncthreads();
        mm_chunk(AsT, WsT, acc, ty << 2, tx << 2);
        __syncthreads();
    }
    __nv_bfloat16* O = (target == 0) ? g_Wq_bf : (target == 1) ? g_Wk_bf
                     : (target == 2) ? g_Wv_bf : g_Wco_bf;
    int m0 = mb * 64 + (tx << 2);
#pragma unroll
    for (int i = 0; i < 4; i++) {
        int nn = nb * 64 + (ty << 2) + i;
        *reinterpret_cast<uint2*>(O + (size_t)nn * M + m0) =
            make_uint2(pack_bf2(acc[i].x, acc[i].y), pack_bf2(acc[i].z, acc[i].w));
    }
}

// ---------------- warp-per-output conditioning kernels ----------------
__global__ void __launch_bounds__(256) k_static_w(const float* __restrict__ st,
                                                  const float* __restrict__ stat_W,
                                                  const float* __restrict__ stat_b) {
    int wid = (blockIdx.x * 256 + threadIdx.x) >> 5;  // B*E warps
    int lane = threadIdx.x & 31;
    int b = wid >> 9, e = wid & 511;
    const float2 av = reinterpret_cast<const float2*>(st + b * DS_)[lane];
    const float2 wv = reinterpret_cast<const float2*>(stat_W + e * DS_)[lane];
    float s = av.x * wv.x + av.y * wv.y;
#pragma unroll
    for (int o = 16; o; o >>= 1) s += __shfl_xor_sync(0xffffffffu, s, o);
    if (lane == 0) g_static_token[wid] = s + stat_b[e];
}
__global__ void __launch_bounds__(256) k_hidden_w(const float* __restrict__ W1,
                                                  const float* __restrict__ b1) {
    int wid = (blockIdx.x * 256 + threadIdx.x) >> 5;  // B*E warps
    int lane = threadIdx.x & 31;
    int b = wid >> 9, e = wid & 511;
    float s = warp_dot512(g_static_token + b * E_, W1 + (size_t)e * E_, lane);
    if (lane == 0) {
        s += b1[e];
        g_hidden[wid] = s >= 0.f ? s : 0.1f * s;
    }
}
__global__ void __launch_bounds__(256) k_film_w(const float* __restrict__ W2,
                                                const float* __restrict__ b2) {
    int wid = (blockIdx.x * 256 + threadIdx.x) >> 5;  // B*C warps
    int lane = threadIdx.x & 31;
    int b = wid >> 8, c = wid & 255;
    float s = warp_dot512(g_hidden + b * E_, W2 + (size_t)c * E_, lane);
    if (lane == 0) g_film[wid] = tanhf(s + b2[c]);
}
// all four bias combinations in one launch: 3*512 + 256 = 1792 warps
__global__ void __launch_bounds__(256) biasc_all(const float* __restrict__ in_proj_W,
                                                 const float* __restrict__ in_proj_b,
                                                 const float* __restrict__ q_b,
                                                 const float* __restrict__ dyn_b,
                                                 const float* __restrict__ ctx_W,
                                                 const float* __restrict__ out_b,
                                                 const float* __restrict__ ctx_b) {
    int wid = (blockIdx.x * 256 + threadIdx.x) >> 5;
    int lane = threadIdx.x & 31;
    int target = wid >> 9;           // 0,1,2 -> in_proj rows; 3 -> ctx
    int n = wid & 511;
    const float* L;
    const float* vec;
    float add;
    float* o;
    if (target < 3) {
        L = in_proj_W + (size_t)target * E_ * E_ + (size_t)n * E_;
        vec = (target == 0) ? q_b : dyn_b;
        add = in_proj_b[target * E_ + n];
        o = (target == 0) ? g_bq : (target == 1) ? g_bk : g_bv;
    } else {
        if (n >= C_) return;
        L = ctx_W + (size_t)n * E_;
        vec = out_b;
        add = ctx_b[n];
        o = g_bco;
    }
    float s = warp_dot512(L, vec, lane);
    if (lane == 0) o[n] = s + add;
}
__global__ void __launch_bounds__(256) stat_kv_w(const float* __restrict__ in_proj_W,
                                                 const float* __restrict__ in_proj_b) {
    int wid = (blockIdx.x * 256 + threadIdx.x) >> 5;  // 2*B*E warps
    int lane = threadIdx.x & 31;
    int which = wid >> 13;
    int r2 = wid & 8191;
    int b = r2 >> 9, e = r2 & 511;
    const float* W = in_proj_W + (size_t)(1 + which) * E_ * E_ + (size_t)e * E_;
    float s = warp_dot512(g_static_token + b * E_, W, lane);
    if (lane == 0) {
        s += in_proj_b[(1 + which) * E_ + e];
        __nv_bfloat16* dst = which ? g_v_bf : g_k_bf;
        dst[((size_t)(b * S1_ + S_)) * E_ + e] = __float2bfloat16(s);
    }
}

// ---------------- converts (outputs selected internally) ----------------
__global__ void __launch_bounds__(256) cvt_dyn_kernel(const float* __restrict__ in, int n4) {
    int i = blockIdx.x * 256 + threadIdx.x;
    if (i < n4) {
        float4 v = reinterpret_cast<const float4*>(in)[i];
        reinterpret_cast<uint2*>(g_dyn_bf)[i] = make_uint2(pack_bf2(v.x, v.y), pack_bf2(v.z, v.w));
    }
}
__global__ void __launch_bounds__(256) xT_kernel(const float* __restrict__ x) {
    __shared__ float t[32][33];
    int h0 = blockIdx.x * 32, c0 = blockIdx.y * 32, b = blockIdx.z;
    int tx = threadIdx.x & 31, ty = threadIdx.x >> 5;
#pragma unroll
    for (int i = 0; i < 4; i++)
        t[ty + 8 * i][tx] = x[((size_t)b * C_ + c0 + ty + 8 * i) * H_ + h0 + tx];
    __syncthreads();
#pragma unroll
    for (int i = 0; i < 4; i++)
        g_xT[((size_t)b * H_ + h0 + ty + 8 * i) * C_ + c0 + tx] = __float2bfloat16(t[tx][ty + 8 * i]);
}

// ---------------- launch ----------------
extern "C" void kernel_launch(void* const* d_in, const int* in_sizes, int n_in,
                              void* d_out, int out_size) {
    const float* x         = (const float*)d_in[0];
    const float* dyn       = (const float*)d_in[1];
    const float* statin    = (const float*)d_in[2];
    const float* dyn_W     = (const float*)d_in[3];
    const float* dyn_b     = (const float*)d_in[4];
    const float* stat_W    = (const float*)d_in[5];
    const float* stat_b    = (const float*)d_in[6];
    const float* film_W1   = (const float*)d_in[7];
    const float* film_b1   = (const float*)d_in[8];
    const float* film_W2   = (const float*)d_in[9];
    const float* film_b2   = (const float*)d_in[10];
    const float* q_W       = (const float*)d_in[11];
    const float* q_b       = (const float*)d_in[12];
    const float* in_proj_W = (const float*)d_in[13];
    const float* in_proj_b = (const float*)d_in[14];
    const float* out_W     = (const float*)d_in[15];
    const float* out_b     = (const float*)d_in[16];
    const float* ctx_W     = (const float*)d_in[17];
    const float* ctx_b     = (const float*)d_in[18];
    const float* bias_tab  = (const float*)d_in[19];
    float* out = (float*)d_out;

    // input conversions (globals referenced ONLY device-side)
    cvt_dyn_kernel<<<(B_ * S_ * DD_ / 4 + 255) / 256, 256>>>(dyn, B_ * S_ * DD_ / 4);
    xT_kernel<<<dim3(32, 8, 16), 256>>>(x);

    // conditioning path (warp-per-output)
    k_static_w<<<(B_ * E_ * 32) / 256, 256>>>(statin, stat_W, stat_b);
    k_hidden_w<<<(B_ * E_ * 32) / 256, 256>>>(film_W1, film_b1);
    k_film_w<<<(B_ * C_ * 32) / 256, 256>>>(film_W2, film_b2);

    // fused weight precompute (bf16 outputs, selected device-side)
    comb_tiled<<<dim3(4, 8), 256>>>(0, in_proj_W, q_W, C_, E_, E_, C_);
    comb_tiled<<<dim3(8, 8), 256>>>(1, in_proj_W + E_ * E_, dyn_W, DD_, E_, E_, DD_);
    comb_tiled<<<dim3(8, 8), 256>>>(2, in_proj_W + 2 * E_ * E_, dyn_W, DD_, E_, E_, DD_);
    comb_tiled<<<dim3(8, 4), 256>>>(3, ctx_W, out_W, E_, E_, E_, E_);
    biasc_all<<<(4 * E_ * 32) / 256, 256>>>(in_proj_W, in_proj_b, q_b, dyn_b, ctx_W, out_b, ctx_b);
    stat_kv_w<<<(2 * B_ * E_ * 32) / 256, 256>>>(in_proj_W, in_proj_b);

    // HMMA projections q/k/v in ONE launch (mode = blockIdx.z)
    hmma_gemm<<<dim3(4, 128, 3), 256>>>(-1, nullptr, nullptr);

    // HMMA flash attention
    attn_hmma<<<dim3(16, NH_, B_), 128>>>(bias_tab);

    // output projection + residual + FiLM
    hmma_gemm<<<dim3(2, 128), 256>>>(3, x, out);

    (void)in_sizes; (void)n_in; (void)out_size;
}

// round 11
// speedup vs baseline: 5.6586x; 1.1424x over previous
#include <cuda_runtime.h>
#include <cuda_bf16.h>
#include <math.h>
#include <stdint.h>

static constexpr int B_ = 16, C_ = 256, H_ = 1024, S_ = 1024, E_ = 512;
static constexpr int NH_ = 8, HD_ = 64, DD_ = 512, DS_ = 64;
static constexpr int S1_ = S_ + 1;
static constexpr int RELM = 2048;

// ---------------- device scratch (NEVER passed from host) ----------------
__device__ float g_static_token[B_ * E_];
__device__ float g_hidden[B_ * E_];
__device__ float g_film[B_ * C_];
__device__ float g_bq[E_], g_bk[E_], g_bv[E_], g_bco[C_];
__device__ __nv_bfloat16 g_q_bf[(size_t)B_ * H_ * E_];
__device__ __nv_bfloat16 g_k_bf[(size_t)B_ * S1_ * E_];
__device__ __nv_bfloat16 g_v_bf[(size_t)B_ * S1_ * E_];
__device__ __nv_bfloat16 g_ctx_bf[(size_t)B_ * H_ * E_];
__device__ __nv_bfloat16 g_dyn_bf[(size_t)B_ * S_ * DD_];
__device__ __nv_bfloat16 g_xT[(size_t)B_ * H_ * C_];
__device__ __nv_bfloat16 g_Wq_bf[E_ * C_];
__device__ __nv_bfloat16 g_Wk_bf[E_ * DD_];
__device__ __nv_bfloat16 g_Wv_bf[E_ * DD_];
__device__ __nv_bfloat16 g_Wco_bf[C_ * E_];

// ---------------- helpers ----------------
__device__ __forceinline__ void mma16816(float* c, const uint32_t a[4], uint32_t b0, uint32_t b1) {
    asm volatile("mma.sync.aligned.m16n8k16.row.col.f32.bf16.bf16.f32 "
                 "{%0,%1,%2,%3},{%4,%5,%6,%7},{%8,%9},{%0,%1,%2,%3};"
                 : "+f"(c[0]), "+f"(c[1]), "+f"(c[2]), "+f"(c[3])
                 : "r"(a[0]), "r"(a[1]), "r"(a[2]), "r"(a[3]), "r"(b0), "r"(b1));
}
__device__ __forceinline__ uint32_t ld32bf(const __nv_bfloat16* p) {
    return *reinterpret_cast<const uint32_t*>(p);
}
__device__ __forceinline__ uint32_t pack_bf2(float a, float b) {
    __nv_bfloat162 h = __floats2bfloat162_rn(a, b);
    return *reinterpret_cast<uint32_t*>(&h);
}
__device__ __forceinline__ uint32_t smem_u32(const void* p) {
    uint32_t a;
    asm("{ .reg .u64 t; cvta.to.shared.u64 t, %1; cvt.u32.u64 %0, t; }" : "=r"(a) : "l"(p));
    return a;
}
__device__ __forceinline__ void cp16(uint32_t dst, const void* src) {
    asm volatile("cp.async.ca.shared.global [%0], [%1], 16;" :: "r"(dst), "l"(src));
}
#define CP_COMMIT() asm volatile("cp.async.commit_group;" ::: "memory")
#define CP_WAIT1()  asm volatile("cp.async.wait_group 1;" ::: "memory")
#define CP_WAIT0()  asm volatile("cp.async.wait_group 0;" ::: "memory")

__device__ __forceinline__ float warp_dot512(const float* __restrict__ a,
                                             const float* __restrict__ w, int lane) {
    float s = 0.f;
#pragma unroll
    for (int i = 0; i < 4; i++) {
        float4 av = *reinterpret_cast<const float4*>(a + lane * 4 + i * 128);
        float4 wv = *reinterpret_cast<const float4*>(w + lane * 4 + i * 128);
        s += av.x * wv.x + av.y * wv.y + av.z * wv.z + av.w * wv.w;
    }
#pragma unroll
    for (int o = 16; o; o >>= 1) s += __shfl_xor_sync(0xffffffffu, s, o);
    return s;
}

// ---------------- HMMA GEMM with cp.async double buffering ----------------
// mode_arg: -1 = qkv combined (mode=blockIdx.z), 3 = out (f32 + residual + film)
static constexpr int GPAD = 40;  // 80B rows; 32 data cols
__global__ void __launch_bounds__(256) hmma_gemm(int mode_arg,
                                                 const float* __restrict__ xin,
                                                 float* __restrict__ outf) {
    __shared__ __nv_bfloat16 sA[2][128 * GPAD];
    __shared__ __nv_bfloat16 sB[2][128 * GPAD];
    int mode = (mode_arg >= 0) ? mode_arg : (int)blockIdx.z;
    const __nv_bfloat16* A = (mode == 0) ? g_xT : (mode == 3) ? g_ctx_bf : g_dyn_bf;
    const __nv_bfloat16* W = (mode == 0) ? g_Wq_bf : (mode == 1) ? g_Wk_bf
                           : (mode == 2) ? g_Wv_bf : g_Wco_bf;
    int lda = (mode == 0) ? C_ : DD_;
    int nk = lda >> 5;
    int tid = threadIdx.x, warp = tid >> 5, lane = tid & 31;
    int g = lane >> 2, c2 = (lane & 3) * 2;
    int wm = warp & 3, wn = warp >> 2;
    int n0 = blockIdx.x * 128, m0 = blockIdx.y * 128;

    uint32_t sAu = smem_u32(&sA[0][0]), sBu = smem_u32(&sB[0][0]);
    const __nv_bfloat16* Ab = A + (size_t)m0 * lda;
    const __nv_bfloat16* Wb = W + (size_t)n0 * lda;
    int ldrow = (tid >> 2), ldseg = (tid & 3);  // row,seg for first 64 rows; +64 rows second pass

    auto issue = [&](int buf, int kc) {
#pragma unroll
        for (int i = 0; i < 2; i++) {
            int row = ldrow + i * 64;
            uint32_t off = (uint32_t)(buf * 128 * GPAD + row * GPAD + ldseg * 8) * 2;
            cp16(sAu + off, Ab + (size_t)row * lda + kc + ldseg * 8);
            cp16(sBu + off, Wb + (size_t)row * lda + kc + ldseg * 8);
        }
    };

    float acc[2][8][4];
#pragma unroll
    for (int i = 0; i < 2; i++)
#pragma unroll
        for (int j = 0; j < 8; j++)
#pragma unroll
            for (int t = 0; t < 4; t++) acc[i][j][t] = 0.f;

    issue(0, 0);
    CP_COMMIT();
    for (int it = 0; it < nk; it++) {
        int buf = it & 1;
        if (it + 1 < nk) {
            issue(buf ^ 1, (it + 1) * 32);
            CP_COMMIT();
            CP_WAIT1();
        } else {
            CP_WAIT0();
        }
        __syncthreads();
#pragma unroll
        for (int ks = 0; ks < 2; ks++) {
            int k0 = ks * 16;
            uint32_t af[2][4];
#pragma unroll
            for (int mf = 0; mf < 2; mf++) {
                const __nv_bfloat16* ap = &sA[buf][(wm * 32 + mf * 16 + g) * GPAD + k0 + c2];
                af[mf][0] = ld32bf(ap);
                af[mf][1] = ld32bf(ap + 8 * GPAD);
                af[mf][2] = ld32bf(ap + 8);
                af[mf][3] = ld32bf(ap + 8 * GPAD + 8);
            }
#pragma unroll
            for (int nf = 0; nf < 8; nf++) {
                const __nv_bfloat16* bp = &sB[buf][(wn * 64 + nf * 8 + g) * GPAD + k0 + c2];
                uint32_t b0 = ld32bf(bp), b1 = ld32bf(bp + 8);
                mma16816(acc[0][nf], af[0], b0, b1);
                mma16816(acc[1][nf], af[1], b0, b1);
            }
        }
        __syncthreads();
    }

    const float* bias = (mode == 0) ? g_bq : (mode == 1) ? g_bk : (mode == 2) ? g_bv : g_bco;
    if (mode <= 2) {
#pragma unroll
        for (int mf = 0; mf < 2; mf++) {
            int r = m0 + wm * 32 + mf * 16 + g;
            __nv_bfloat16* d0;
            __nv_bfloat16* d1;
            if (mode == 0) {
                d0 = g_q_bf + (size_t)r * E_;
                d1 = g_q_bf + (size_t)(r + 8) * E_;
            } else {
                __nv_bfloat16* base = (mode == 1) ? g_k_bf : g_v_bf;
                int b0r = r >> 10, s0r = r & 1023;
                int b1r = (r + 8) >> 10, s1r = (r + 8) & 1023;
                d0 = base + ((size_t)(b0r * S1_ + s0r)) * E_;
                d1 = base + ((size_t)(b1r * S1_ + s1r)) * E_;
            }
#pragma unroll
            for (int nf = 0; nf < 8; nf++) {
                int cc = n0 + wn * 64 + nf * 8 + c2;
                float bb0 = bias[cc], bb1 = bias[cc + 1];
                *reinterpret_cast<uint32_t*>(d0 + cc) = pack_bf2(acc[mf][nf][0] + bb0, acc[mf][nf][1] + bb1);
                *reinterpret_cast<uint32_t*>(d1 + cc) = pack_bf2(acc[mf][nf][2] + bb0, acc[mf][nf][3] + bb1);
            }
        }
    } else {
#pragma unroll
        for (int mf = 0; mf < 2; mf++) {
            int r = m0 + wm * 32 + mf * 16 + g;
            int bb = r >> 10;
            int h0v = r & 1023;
#pragma unroll
            for (int nf = 0; nf < 8; nf++) {
                int cc = n0 + wn * 64 + nf * 8 + c2;
#pragma unroll
                for (int u = 0; u < 2; u++) {
                    int c = cc + u;
                    float sc = 1.f + g_film[bb * C_ + c];
                    float bco = bias[c];
                    size_t o0 = ((size_t)bb * C_ + c) * H_ + h0v;
                    size_t o1 = o0 + 8;
                    outf[o0] = (xin[o0] + acc[mf][nf][u] + bco) * sc;
                    outf[o1] = (xin[o1] + acc[mf][nf][2 + u] + bco) * sc;
                }
            }
        }
    }
}

// ---------------- HMMA flash attention: 256 threads, 128-row Q tile ----------------
static constexpr int KPAD = 72;
__global__ void __launch_bounds__(256) attn_hmma(const float* __restrict__ bias_table) {
    __shared__ __nv_bfloat16 smK[64 * KPAD];   // [key][dim]
    __shared__ __nv_bfloat16 smVT[64 * KPAD];  // [dim][key ^ ((dim>>3)*8)]
    int qt = 7 - (int)blockIdx.x;
    int n = blockIdx.y, b = blockIdx.z;
    int h0 = qt << 7;
    int tid = threadIdx.x, warp = tid >> 5, lane = tid & 31;
    int g = lane >> 2, c2 = (lane & 3) * 2;
    int hg = h0 + warp * 16 + g, hh = hg + 8;

    uint32_t qa[4][4];
    {
        const __nv_bfloat16* qg = g_q_bf + ((size_t)(b * H_) + hg) * E_ + n * HD_;
        const __nv_bfloat16* qh = qg + 8 * E_;
#pragma unroll
        for (int j = 0; j < 4; j++) {
            qa[j][0] = ld32bf(qg + j * 16 + c2);
            qa[j][1] = ld32bf(qh + j * 16 + c2);
            qa[j][2] = ld32bf(qg + j * 16 + c2 + 8);
            qa[j][3] = ld32bf(qh + j * 16 + c2 + 8);
        }
    }

    float m0 = -1e30f, m1 = -1e30f, l0 = 0.f, l1 = 0.f;
    float oa[8][4];
#pragma unroll
    for (int j = 0; j < 8; j++)
#pragma unroll
        for (int t = 0; t < 4; t++) oa[j][t] = 0.f;

    int nit = 2 * qt + 2;  // k-tiles 0..2qt+1, then static at it==nit
    for (int it = 0; it <= nit; it++) {
        bool last = (it == nit);
        int k0 = last ? S_ : (it << 6);

        if (!last) {
            const __nv_bfloat16* kg = g_k_bf + ((size_t)(b * S1_ + k0)) * E_ + n * HD_;
            const __nv_bfloat16* vg = g_v_bf + ((size_t)(b * S1_ + k0)) * E_ + n * HD_;
            // K: [key][dim], 64x64, 512 uint4 / 256 thr
#pragma unroll
            for (int i = 0; i < 2; i++) {
                int idx = tid + i * 256;
                int row = idx >> 3, seg = idx & 7;
                *reinterpret_cast<uint4*>(&smK[row * KPAD + seg * 8]) =
                    *reinterpret_cast<const uint4*>(kg + (size_t)row * E_ + seg * 8);
            }
            // V transpose: thread owns key pair (2kp,2kp+1) x dims dj..dj+7
            {
                int kp = tid >> 3;
                int dj = (tid & 7) * 8;
                int colbase = (2 * kp) ^ (((unsigned)(tid & 7)) << 3);  // (dim>>3)&7 == tid&7
                uint4 u0 = *reinterpret_cast<const uint4*>(vg + (size_t)(2 * kp) * E_ + dj);
                uint4 u1 = *reinterpret_cast<const uint4*>(vg + (size_t)(2 * kp + 1) * E_ + dj);
                const uint16_t* e0 = reinterpret_cast<const uint16_t*>(&u0);
                const uint16_t* e1 = reinterpret_cast<const uint16_t*>(&u1);
#pragma unroll
                for (int t = 0; t < 8; t++) {
                    uint32_t pk = (uint32_t)e0[t] | ((uint32_t)e1[t] << 16);
                    *reinterpret_cast<uint32_t*>(&smVT[(dj + t) * KPAD + colbase]) = pk;
                }
            }
        } else {
#pragma unroll
            for (int i = 0; i < 3; i++) {
                int idx = tid + i * 256;
                if (idx < 64 * KPAD / 8) {
                    *reinterpret_cast<uint4*>(&smK[idx * 8]) = make_uint4(0, 0, 0, 0);
                    *reinterpret_cast<uint4*>(&smVT[idx * 8]) = make_uint4(0, 0, 0, 0);
                }
            }
            __syncthreads();
            if (tid < 64) {
                const __nv_bfloat16 kv = g_k_bf[((size_t)(b * S1_ + S_)) * E_ + n * HD_ + tid];
                const __nv_bfloat16 vv = g_v_bf[((size_t)(b * S1_ + S_)) * E_ + n * HD_ + tid];
                smK[0 * KPAD + tid] = kv;
                int colv = 0 ^ (((tid >> 3) & 7) << 3);
                uint32_t pk = (uint32_t)(*reinterpret_cast<const uint16_t*>(&vv));
                *reinterpret_cast<uint32_t*>(&smVT[tid * KPAD + colv]) = pk;
            }
        }
        __syncthreads();

        // scores: Q @ K^T
        float sc[8][4];
#pragma unroll
        for (int j = 0; j < 8; j++)
#pragma unroll
            for (int t = 0; t < 4; t++) sc[j][t] = 0.f;
#pragma unroll
        for (int j = 0; j < 4; j++) {
#pragma unroll
            for (int nf = 0; nf < 8; nf++) {
                const __nv_bfloat16* bp = &smK[(nf * 8 + g) * KPAD + j * 16 + c2];
                mma16816(sc[nf], qa[j], ld32bf(bp), ld32bf(bp + 8));
            }
        }

        // online softmax
        float vg16[16], vh16[16];
        float mlg = -1e30f, mlh = -1e30f;
#pragma unroll
        for (int nf = 0; nf < 8; nf++) {
#pragma unroll
            for (int u = 0; u < 2; u++) {
                int col = nf * 8 + c2 + u;
                int kk = k0 + col;
                bool inb = (kk < S1_);
                bool okg = inb && (kk >= S_ || kk <= hg);
                bool okh = inb && (kk >= S_ || kk <= hh);
                float vgv = okg ? sc[nf][u] * 0.125f + __ldg(bias_table + (hg - kk + RELM - 1)) : -1e30f;
                float vhv = okh ? sc[nf][2 + u] * 0.125f + __ldg(bias_table + (hh - kk + RELM - 1)) : -1e30f;
                vg16[nf * 2 + u] = vgv;
                vh16[nf * 2 + u] = vhv;
                mlg = fmaxf(mlg, vgv);
                mlh = fmaxf(mlh, vhv);
            }
        }
        mlg = fmaxf(mlg, __shfl_xor_sync(0xffffffffu, mlg, 1));
        mlg = fmaxf(mlg, __shfl_xor_sync(0xffffffffu, mlg, 2));
        mlh = fmaxf(mlh, __shfl_xor_sync(0xffffffffu, mlh, 1));
        mlh = fmaxf(mlh, __shfl_xor_sync(0xffffffffu, mlh, 2));
        float mng = fmaxf(m0, mlg), mnh = fmaxf(m1, mlh);
        float cg = __expf(m0 - mng), ch = __expf(m1 - mnh);
        uint32_t pkg[8], pkh[8];
        float sg = 0.f, sh = 0.f;
#pragma unroll
        for (int nf = 0; nf < 8; nf++) {
            float p0 = __expf(vg16[nf * 2 + 0] - mng);
            float p1 = __expf(vg16[nf * 2 + 1] - mng);
            float p2 = __expf(vh16[nf * 2 + 0] - mnh);
            float p3 = __expf(vh16[nf * 2 + 1] - mnh);
            sg += p0 + p1;
            sh += p2 + p3;
            pkg[nf] = pack_bf2(p0, p1);
            pkh[nf] = pack_bf2(p2, p3);
        }
        sg += __shfl_xor_sync(0xffffffffu, sg, 1);
        sg += __shfl_xor_sync(0xffffffffu, sg, 2);
        sh += __shfl_xor_sync(0xffffffffu, sh, 1);
        sh += __shfl_xor_sync(0xffffffffu, sh, 2);
        l0 = l0 * cg + sg;
        l1 = l1 * ch + sh;
        m0 = mng;
        m1 = mnh;
#pragma unroll
        for (int nf = 0; nf < 8; nf++) {
            oa[nf][0] *= cg; oa[nf][1] *= cg;
            oa[nf][2] *= ch; oa[nf][3] *= ch;
        }

        // O += P @ V  (B operand from swizzled V^T)
#pragma unroll
        for (int j = 0; j < 4; j++) {
            uint32_t pa[4] = {pkg[2 * j], pkh[2 * j], pkg[2 * j + 1], pkh[2 * j + 1]};
#pragma unroll
            for (int nf = 0; nf < 8; nf++) {
                int rowd = nf * 8 + g;
                int sw = (nf & 7) << 3;
                int col0 = (j * 16 + c2) ^ sw;
                int col1 = (j * 16 + c2 + 8) ^ sw;
                uint32_t b0 = ld32bf(&smVT[rowd * KPAD + col0]);
                uint32_t b1 = ld32bf(&smVT[rowd * KPAD + col1]);
                mma16816(oa[nf], pa, b0, b1);
            }
        }
        __syncthreads();
    }

    float i0 = 1.f / l0, i1 = 1.f / l1;
    __nv_bfloat16* d0 = g_ctx_bf + ((size_t)(b * H_) + hg) * E_ + n * HD_;
    __nv_bfloat16* d1 = d0 + 8 * E_;
#pragma unroll
    for (int nf = 0; nf < 8; nf++) {
        int d = nf * 8 + c2;
        *reinterpret_cast<uint32_t*>(d0 + d) = pack_bf2(oa[nf][0] * i0, oa[nf][1] * i0);
        *reinterpret_cast<uint32_t*>(d1 + d) = pack_bf2(oa[nf][2] * i1, oa[nf][3] * i1);
    }
}

// ---------------- SIMT fp32 64x64 tile (weight combos, merged) ----------------
__device__ __forceinline__ int swz(int r, int c) {
    return (r << 6) + (((c & 60) ^ ((r & 15) << 2)) | (c & 3));
}
__device__ __forceinline__ int swz4(int r, int c4) { return (r << 6) + (c4 ^ ((r & 15) << 2)); }
__device__ __forceinline__ void load_tileT_rm(float* sm, const float* g, int ld) {
    int tid = threadIdx.x;
#pragma unroll
    for (int i = 0; i < 4; i++) {
        int fi = tid + (i << 8);
        int m = fi >> 4, k4 = (fi & 15) << 2;
        float4 v = *reinterpret_cast<const float4*>(g + (size_t)m * ld + k4);
        sm[swz(k4 + 0, m)] = v.x; sm[swz(k4 + 1, m)] = v.y;
        sm[swz(k4 + 2, m)] = v.z; sm[swz(k4 + 3, m)] = v.w;
    }
}
__device__ __forceinline__ void load_tileT_cm(float* sm, const float* g, int ldk) {
    int tid = threadIdx.x;
#pragma unroll
    for (int i = 0; i < 4; i++) {
        int fi = tid + (i << 8);
        int k = fi >> 4, m4 = (fi & 15) << 2;
        float4 v = *reinterpret_cast<const float4*>(g + (size_t)k * ldk + m4);
        *reinterpret_cast<float4*>(sm + swz4(k, m4)) = v;
    }
}
__device__ __forceinline__ void mm_chunk(const float* __restrict__ AsT, const float* __restrict__ WsT,
                                         float4 acc[4], int m0, int n0) {
#pragma unroll 8
    for (int k = 0; k < 64; k++) {
        float4 a = *reinterpret_cast<const float4*>(AsT + swz4(k, m0));
        float4 w = *reinterpret_cast<const float4*>(WsT + swz4(k, n0));
        acc[0].x += a.x * w.x; acc[0].y += a.x * w.y; acc[0].z += a.x * w.z; acc[0].w += a.x * w.w;
        acc[1].x += a.y * w.x; acc[1].y += a.y * w.y; acc[1].z += a.y * w.z; acc[1].w += a.y * w.w;
        acc[2].x += a.z * w.x; acc[2].y += a.z * w.y; acc[2].z += a.z * w.z; acc[2].w += a.z * w.w;
        acc[3].x += a.w * w.x; acc[3].y += a.w * w.y; acc[3].z += a.w * w.z; acc[3].w += a.w * w.w;
    }
}
// all 4 weight combos in ONE launch: 192 blocks total
__global__ void __launch_bounds__(256) comb_all(const float* __restrict__ in_proj_W,
                                                const float* __restrict__ q_W,
                                                const float* __restrict__ dyn_W,
                                                const float* __restrict__ ctx_W,
                                                const float* __restrict__ out_W) {
    __shared__ float AsT[4096], WsT[4096];
    int bid = blockIdx.x;
    int target, mb, nb, M, K, ldL, ldR;
    const float* L;
    const float* R;
    if (bid < 32) {
        target = 0; mb = bid & 3; nb = bid >> 2;
        L = in_proj_W; R = q_W; M = C_; K = E_; ldL = E_; ldR = C_;
    } else if (bid < 96) {
        int l = bid - 32;
        target = 1; mb = l & 7; nb = l >> 3;
        L = in_proj_W + E_ * E_; R = dyn_W; M = DD_; K = E_; ldL = E_; ldR = DD_;
    } else if (bid < 160) {
        int l = bid - 96;
        target = 2; mb = l & 7; nb = l >> 3;
        L = in_proj_W + 2 * E_ * E_; R = dyn_W; M = DD_; K = E_; ldL = E_; ldR = DD_;
    } else {
        int l = bid - 160;
        target = 3; mb = l & 7; nb = l >> 3;
        L = ctx_W; R = out_W; M = E_; K = E_; ldL = E_; ldR = E_;
    }
    int tid = threadIdx.x, ty = tid >> 4, tx = tid & 15;
    const float* Lg = L + (size_t)(nb * 64) * ldL;
    const float* Rg = R + mb * 64;
    float4 acc[4] = {};
    for (int kc = 0; kc < K; kc += 64) {
        load_tileT_rm(AsT, Lg + kc, ldL);
        load_tileT_cm(WsT, Rg + (size_t)kc * ldR, ldR);
        __syncthreads();
        mm_chunk(AsT, WsT, acc, ty << 2, tx << 2);
        __syncthreads();
    }
    __nv_bfloat16* O = (target == 0) ? g_Wq_bf : (target == 1) ? g_Wk_bf
                     : (target == 2) ? g_Wv_bf : g_Wco_bf;
    int m0 = mb * 64 + (tx << 2);
#pragma unroll
    for (int i = 0; i < 4; i++) {
        int nn = nb * 64 + (ty << 2) + i;
        *reinterpret_cast<uint2*>(O + (size_t)nn * M + m0) =
            make_uint2(pack_bf2(acc[i].x, acc[i].y), pack_bf2(acc[i].z, acc[i].w));
    }
}

// ---------------- warp-per-output conditioning kernels ----------------
__global__ void __launch_bounds__(256) k_static_w(const float* __restrict__ st,
                                                  const float* __restrict__ stat_W,
                                                  const float* __restrict__ stat_b) {
    int wid = (blockIdx.x * 256 + threadIdx.x) >> 5;
    int lane = threadIdx.x & 31;
    int b = wid >> 9, e = wid & 511;
    const float2 av = reinterpret_cast<const float2*>(st + b * DS_)[lane];
    const float2 wv = reinterpret_cast<const float2*>(stat_W + e * DS_)[lane];
    float s = av.x * wv.x + av.y * wv.y;
#pragma unroll
    for (int o = 16; o; o >>= 1) s += __shfl_xor_sync(0xffffffffu, s, o);
    if (lane == 0) g_static_token[wid] = s + stat_b[e];
}
__global__ void __launch_bounds__(256) k_hidden_w(const float* __restrict__ W1,
                                                  const float* __restrict__ b1) {
    int wid = (blockIdx.x * 256 + threadIdx.x) >> 5;
    int lane = threadIdx.x & 31;
    int b = wid >> 9, e = wid & 511;
    float s = warp_dot512(g_static_token + b * E_, W1 + (size_t)e * E_, lane);
    if (lane == 0) {
        s += b1[e];
        g_hidden[wid] = s >= 0.f ? s : 0.1f * s;
    }
}
__global__ void __launch_bounds__(256) k_film_w(const float* __restrict__ W2,
                                                const float* __restrict__ b2) {
    int wid = (blockIdx.x * 256 + threadIdx.x) >> 5;
    int lane = threadIdx.x & 31;
    int b = wid >> 8, c = wid & 255;
    float s = warp_dot512(g_hidden + b * E_, W2 + (size_t)c * E_, lane);
    if (lane == 0) g_film[wid] = tanhf(s + b2[c]);
}
__global__ void __launch_bounds__(256) biasc_all(const float* __restrict__ in_proj_W,
                                                 const float* __restrict__ in_proj_b,
                                                 const float* __restrict__ q_b,
                                                 const float* __restrict__ dyn_b,
                                                 const float* __restrict__ ctx_W,
                                                 const float* __restrict__ out_b,
                                                 const float* __restrict__ ctx_b) {
    int wid = (blockIdx.x * 256 + threadIdx.x) >> 5;
    int lane = threadIdx.x & 31;
    int target = wid >> 9;
    int n = wid & 511;
    const float* L;
    const float* vec;
    float add;
    float* o;
    if (target < 3) {
        L = in_proj_W + (size_t)target * E_ * E_ + (size_t)n * E_;
        vec = (target == 0) ? q_b : dyn_b;
        add = in_proj_b[target * E_ + n];
        o = (target == 0) ? g_bq : (target == 1) ? g_bk : g_bv;
    } else {
        if (n >= C_) return;
        L = ctx_W + (size_t)n * E_;
        vec = out_b;
        add = ctx_b[n];
        o = g_bco;
    }
    float s = warp_dot512(L, vec, lane);
    if (lane == 0) o[n] = s + add;
}
__global__ void __launch_bounds__(256) stat_kv_w(const float* __restrict__ in_proj_W,
                                                 const float* __restrict__ in_proj_b) {
    int wid = (blockIdx.x * 256 + threadIdx.x) >> 5;
    int lane = threadIdx.x & 31;
    int which = wid >> 13;
    int r2 = wid & 8191;
    int b = r2 >> 9, e = r2 & 511;
    const float* W = in_proj_W + (size_t)(1 + which) * E_ * E_ + (size_t)e * E_;
    float s = warp_dot512(g_static_token + b * E_, W, lane);
    if (lane == 0) {
        s += in_proj_b[(1 + which) * E_ + e];
        __nv_bfloat16* dst = which ? g_v_bf : g_k_bf;
        dst[((size_t)(b * S1_ + S_)) * E_ + e] = __float2bfloat16(s);
    }
}

// ---------------- converts ----------------
__global__ void __launch_bounds__(256) cvt_dyn_kernel(const float* __restrict__ in, int n4) {
    int i = blockIdx.x * 256 + threadIdx.x;
    if (i < n4) {
        float4 v = reinterpret_cast<const float4*>(in)[i];
        reinterpret_cast<uint2*>(g_dyn_bf)[i] = make_uint2(pack_bf2(v.x, v.y), pack_bf2(v.z, v.w));
    }
}
__global__ void __launch_bounds__(256) xT_kernel(const float* __restrict__ x) {
    __shared__ float t[32][33];
    int h0 = blockIdx.x * 32, c0 = blockIdx.y * 32, b = blockIdx.z;
    int tx = threadIdx.x & 31, ty = threadIdx.x >> 5;
#pragma unroll
    for (int i = 0; i < 4; i++)
        t[ty + 8 * i][tx] = x[((size_t)b * C_ + c0 + ty + 8 * i) * H_ + h0 + tx];
    __syncthreads();
#pragma unroll
    for (int i = 0; i < 4; i++)
        g_xT[((size_t)b * H_ + h0 + ty + 8 * i) * C_ + c0 + tx] = __float2bfloat16(t[tx][ty + 8 * i]);
}

// ---------------- launch ----------------
extern "C" void kernel_launch(void* const* d_in, const int* in_sizes, int n_in,
                              void* d_out, int out_size) {
    const float* x         = (const float*)d_in[0];
    const float* dyn       = (const float*)d_in[1];
    const float* statin    = (const float*)d_in[2];
    const float* dyn_W     = (const float*)d_in[3];
    const float* dyn_b     = (const float*)d_in[4];
    const float* stat_W    = (const float*)d_in[5];
    const float* stat_b    = (const float*)d_in[6];
    const float* film_W1   = (const float*)d_in[7];
    const float* film_b1   = (const float*)d_in[8];
    const float* film_W2   = (const float*)d_in[9];
    const float* film_b2   = (const float*)d_in[10];
    const float* q_W       = (const float*)d_in[11];
    const float* q_b       = (const float*)d_in[12];
    const float* in_proj_W = (const float*)d_in[13];
    const float* in_proj_b = (const float*)d_in[14];
    const float* out_W     = (const float*)d_in[15];
    const float* out_b     = (const float*)d_in[16];
    const float* ctx_W     = (const float*)d_in[17];
    const float* ctx_b     = (const float*)d_in[18];
    const float* bias_tab  = (const float*)d_in[19];
    float* out = (float*)d_out;

    // input conversions
    cvt_dyn_kernel<<<(B_ * S_ * DD_ / 4 + 255) / 256, 256>>>(dyn, B_ * S_ * DD_ / 4);
    xT_kernel<<<dim3(32, 8, 16), 256>>>(x);

    // conditioning path (warp-per-output)
    k_static_w<<<(B_ * E_ * 32) / 256, 256>>>(statin, stat_W, stat_b);
    k_hidden_w<<<(B_ * E_ * 32) / 256, 256>>>(film_W1, film_b1);
    k_film_w<<<(B_ * C_ * 32) / 256, 256>>>(film_W2, film_b2);

    // fused weight precompute, ONE launch
    comb_all<<<192, 256>>>(in_proj_W, q_W, dyn_W, ctx_W, out_W);
    biasc_all<<<(4 * E_ * 32) / 256, 256>>>(in_proj_W, in_proj_b, q_b, dyn_b, ctx_W, out_b, ctx_b);
    stat_kv_w<<<(2 * B_ * E_ * 32) / 256, 256>>>(in_proj_W, in_proj_b);

    // HMMA projections q/k/v (cp.async pipelined) in ONE launch
    hmma_gemm<<<dim3(4, 128, 3), 256>>>(-1, nullptr, nullptr);

    // HMMA flash attention: 128-row Q tiles, 256 threads
    attn_hmma<<<dim3(8, NH_, B_), 256>>>(bias_tab);

    // output projection + residual + FiLM
    hmma_gemm<<<dim3(2, 128), 256>>>(3, x, out);

    (void)in_sizes; (void)n_in; (void)out_size;
}